// round 1
// baseline (speedup 1.0000x reference)
#include <cuda_runtime.h>
#include <cuda_bf16.h>

#define B_ 512
#define T_ 256
#define C_ 384
#define H_ 64

// scratch for q/k/v projections (allocation-free: device globals)
__device__ float g_q[B_ * T_ * H_];
__device__ float g_k[B_ * T_ * H_];
__device__ float g_v[B_ * T_ * H_];

// ---------------------------------------------------------------------------
// Kernel 1: QKV projection.  out = x[131072,384] @ W[384,64]
// blockIdx.y selects Wq/Wk/Wv.  BM=128 rows, BN=64 (=H), BK=16.
// 256 threads as 16x16, microtile 8 rows x 4 cols, vectorized LDS.
// ---------------------------------------------------------------------------
#define BM 128
#define BK 16

__global__ __launch_bounds__(256) void qkv_gemm(const float* __restrict__ x,
                                                const float* __restrict__ Wq,
                                                const float* __restrict__ Wk,
                                                const float* __restrict__ Wv) {
    __shared__ float As[BK][BM + 4];   // A transposed: As[k][m], pad 4 keeps f4 alignment
    __shared__ float Bs[BK][H_];       // Bs[k][n]

    const float* W;
    float* out;
    if (blockIdx.y == 0)      { W = Wq; out = g_q; }
    else if (blockIdx.y == 1) { W = Wk; out = g_k; }
    else                      { W = Wv; out = g_v; }

    const int tid = threadIdx.x;
    const int tx = tid & 15;       // output col group (4 cols)
    const int ty = tid >> 4;       // output row group (8 rows)
    const int row0 = blockIdx.x * BM;

    float acc[8][4];
#pragma unroll
    for (int i = 0; i < 8; i++)
#pragma unroll
        for (int j = 0; j < 4; j++) acc[i][j] = 0.f;

    for (int k0 = 0; k0 < C_; k0 += BK) {
        // A tile 128x16, loaded as float4 along K, stored transposed
#pragma unroll
        for (int i = 0; i < 2; i++) {
            int v  = tid + i * 256;        // 512 float4 slots
            int r  = v >> 2;               // row 0..127
            int cf = v & 3;                // float4 group within the 16 K-cols
            float4 a = *(const float4*)(x + (size_t)(row0 + r) * C_ + k0 + cf * 4);
            As[cf * 4 + 0][r] = a.x;
            As[cf * 4 + 1][r] = a.y;
            As[cf * 4 + 2][r] = a.z;
            As[cf * 4 + 3][r] = a.w;
        }
        // B tile 16x64
        {
            int r = tid >> 4, cf = tid & 15;
            *(float4*)(&Bs[r][cf * 4]) =
                *(const float4*)(W + (size_t)(k0 + r) * H_ + cf * 4);
        }
        __syncthreads();

#pragma unroll
        for (int kk = 0; kk < BK; kk++) {
            float4 a0 = *(const float4*)(&As[kk][ty * 8]);
            float4 a1 = *(const float4*)(&As[kk][ty * 8 + 4]);
            float4 b  = *(const float4*)(&Bs[kk][tx * 4]);
            float av[8] = {a0.x, a0.y, a0.z, a0.w, a1.x, a1.y, a1.z, a1.w};
            float bv[4] = {b.x, b.y, b.z, b.w};
#pragma unroll
            for (int i = 0; i < 8; i++)
#pragma unroll
                for (int j = 0; j < 4; j++) acc[i][j] += av[i] * bv[j];
        }
        __syncthreads();
    }

#pragma unroll
    for (int i = 0; i < 8; i++) {
        float4 o = make_float4(acc[i][0], acc[i][1], acc[i][2], acc[i][3]);
        *(float4*)(out + (size_t)(row0 + ty * 8 + i) * H_ + tx * 4) = o;
    }
}

// ---------------------------------------------------------------------------
// Kernel 2: causal attention for one (batch, 64-query tile).
// grid = (512, 4), 256 threads.  Scores live in SMEM; only key tiles
// kt <= qt are ever touched (causal tile skipping).
// ---------------------------------------------------------------------------
#define SSTR 260                      // sS row stride (pad 4: bank-stagger + f4 align)
#define KSTR 68                       // sQ/sKV row stride
#define SMEM2 ((2 * 64 * KSTR + 64 * SSTR) * 4)   // 101376 bytes

__global__ __launch_bounds__(256) void attn(float* __restrict__ out) {
    extern __shared__ float sm[];
    float* sQ  = sm;                  // [64 dims][KSTR] : Q transposed  sQ[k][m]
    float* sKV = sm + 64 * KSTR;      // K transposed sKV[k][n]  /  V row-major sKV[key][d]
    float* sS  = sm + 2 * 64 * KSTR;  // [64 q][SSTR] scores / probabilities

    const int b    = blockIdx.x;
    const int qt   = blockIdx.y;
    const int q0   = qt * 64;
    const int tid  = threadIdx.x;
    const int tx   = tid & 15;
    const int ty   = tid >> 4;
    const int lane = tid & 31;
    const int wid  = tid >> 5;

    const float* Q = g_q + ((size_t)b * T_ + q0) * H_;
    const float* K = g_k + (size_t)b * T_ * H_;
    const float* V = g_v + (size_t)b * T_ * H_;

    // load Q tile (64x64) transposed into sQ[k][m]
#pragma unroll
    for (int i = 0; i < 4; i++) {
        int v  = tid + i * 256;       // 1024 float4 slots
        int r  = v >> 4;              // query row 0..63
        int cf = v & 15;              // float4 group along dim
        float4 a = *(const float4*)(Q + r * H_ + cf * 4);
        sQ[(cf * 4 + 0) * KSTR + r] = a.x;
        sQ[(cf * 4 + 1) * KSTR + r] = a.y;
        sQ[(cf * 4 + 2) * KSTR + r] = a.z;
        sQ[(cf * 4 + 3) * KSTR + r] = a.w;
    }

    // ---- Phase A: S = Q K^T * scale, causal-masked, into sS ----
    for (int kt = 0; kt <= qt; kt++) {
        __syncthreads();              // sKV free (and first iter: sQ visible after next sync)
#pragma unroll
        for (int i = 0; i < 4; i++) { // load K tile transposed: sKV[k][key]
            int v  = tid + i * 256;
            int r  = v >> 4;
            int cf = v & 15;
            float4 a = *(const float4*)(K + (kt * 64 + r) * H_ + cf * 4);
            sKV[(cf * 4 + 0) * KSTR + r] = a.x;
            sKV[(cf * 4 + 1) * KSTR + r] = a.y;
            sKV[(cf * 4 + 2) * KSTR + r] = a.z;
            sKV[(cf * 4 + 3) * KSTR + r] = a.w;
        }
        __syncthreads();

        float s[4][4];
#pragma unroll
        for (int i = 0; i < 4; i++)
#pragma unroll
            for (int j = 0; j < 4; j++) s[i][j] = 0.f;

#pragma unroll
        for (int kk = 0; kk < 64; kk++) {
            float4 a = *(const float4*)(&sQ[kk * KSTR + ty * 4]);
            float4 bK = *(const float4*)(&sKV[kk * KSTR + tx * 4]);
            float av[4] = {a.x, a.y, a.z, a.w};
            float bv[4] = {bK.x, bK.y, bK.z, bK.w};
#pragma unroll
            for (int i = 0; i < 4; i++)
#pragma unroll
                for (int j = 0; j < 4; j++) s[i][j] += av[i] * bv[j];
        }

#pragma unroll
        for (int i = 0; i < 4; i++) {
            int gq = q0 + ty * 4 + i;
#pragma unroll
            for (int j = 0; j < 4; j++) {
                int gk = kt * 64 + tx * 4 + j;
                sS[(ty * 4 + i) * SSTR + gk] =
                    (gk <= gq) ? s[i][j] * 0.125f : -1e30f;
            }
        }
    }
    __syncthreads();

    // ---- Phase B: row softmax (warp per row, 8 rows per warp) ----
    const int nk = (qt + 1) * 64;
    for (int r = wid; r < 64; r += 8) {
        float m = -1e30f;
        for (int c = lane; c < nk; c += 32) m = fmaxf(m, sS[r * SSTR + c]);
#pragma unroll
        for (int o = 16; o; o >>= 1) m = fmaxf(m, __shfl_xor_sync(0xFFFFFFFFu, m, o));
        float sum = 0.f;
        for (int c = lane; c < nk; c += 32) {
            float e = __expf(sS[r * SSTR + c] - m);
            sS[r * SSTR + c] = e;
            sum += e;
        }
#pragma unroll
        for (int o = 16; o; o >>= 1) sum += __shfl_xor_sync(0xFFFFFFFFu, sum, o);
        float inv = 1.f / sum;
        for (int c = lane; c < nk; c += 32) sS[r * SSTR + c] *= inv;
    }
    __syncthreads();

    // ---- Phase C: O = P V ----
    float o[4][4];
#pragma unroll
    for (int i = 0; i < 4; i++)
#pragma unroll
        for (int j = 0; j < 4; j++) o[i][j] = 0.f;

    for (int kt = 0; kt <= qt; kt++) {
#pragma unroll
        for (int i = 0; i < 4; i++) {   // load V tile row-major: sKV[key][d]
            int v  = tid + i * 256;
            int r  = v >> 4;
            int cf = v & 15;
            *(float4*)(&sKV[r * KSTR + cf * 4]) =
                *(const float4*)(V + (kt * 64 + r) * H_ + cf * 4);
        }
        __syncthreads();
#pragma unroll
        for (int kk = 0; kk < 64; kk++) {
            float4 bV = *(const float4*)(&sKV[kk * KSTR + tx * 4]);
            float bv[4] = {bV.x, bV.y, bV.z, bV.w};
            float av[4];
#pragma unroll
            for (int i = 0; i < 4; i++) av[i] = sS[(ty * 4 + i) * SSTR + kt * 64 + kk];
#pragma unroll
            for (int i = 0; i < 4; i++)
#pragma unroll
                for (int j = 0; j < 4; j++) o[i][j] += av[i] * bv[j];
        }
        __syncthreads();                // sKV free for next tile
    }

#pragma unroll
    for (int i = 0; i < 4; i++) {
        float4 ov = make_float4(o[i][0], o[i][1], o[i][2], o[i][3]);
        *(float4*)(out + ((size_t)b * T_ + q0 + ty * 4 + i) * H_ + tx * 4) = ov;
    }
}

// ---------------------------------------------------------------------------
extern "C" void kernel_launch(void* const* d_in, const int* in_sizes, int n_in,
                              void* d_out, int out_size) {
    const float* x  = (const float*)d_in[0];
    const float* Wq = (const float*)d_in[1];
    const float* Wk = (const float*)d_in[2];
    const float* Wv = (const float*)d_in[3];
    float* out = (float*)d_out;

    (void)in_sizes; (void)n_in; (void)out_size;

    cudaFuncSetAttribute(attn, cudaFuncAttributeMaxDynamicSharedMemorySize, SMEM2);

    dim3 g1((B_ * T_) / BM, 3);
    qkv_gemm<<<g1, 256>>>(x, Wq, Wk, Wv);

    dim3 g2(B_, T_ / 64);
    attn<<<g2, 256, SMEM2>>>(out);
}

// round 3
// speedup vs baseline: 1.5496x; 1.5496x over previous
#include <cuda_runtime.h>
#include <cuda_bf16.h>
#include <cstdint>

#define B_ 512
#define T_ 256
#define C_ 384
#define H_ 64
#define NTOT 192

// fp32 q/k/v scratch
__device__ float g_q[B_ * T_ * H_];
__device__ float g_k[B_ * T_ * H_];
__device__ float g_v[B_ * T_ * H_];
// pre-split weights, K-major: row n (0..191 = q|k|v), gW[n][384]
__device__ __align__(16) __nv_bfloat16 gWhi[NTOT * C_];
__device__ __align__(16) __nv_bfloat16 gWlo[NTOT * C_];

__device__ __forceinline__ void split1(float v, __nv_bfloat16& h, __nv_bfloat16& l) {
    h = __float2bfloat16(v);
    l = __float2bfloat16(v - __bfloat162float(h));
}
__device__ __forceinline__ uint32_t pack2(__nv_bfloat16 a, __nv_bfloat16 b) {
    __nv_bfloat162 t = __halves2bfloat162(a, b);
    uint32_t u; memcpy(&u, &t, 4); return u;
}
__device__ __forceinline__ void mma16816(float* d, const uint32_t* a,
                                         uint32_t b0, uint32_t b1) {
    asm volatile(
        "mma.sync.aligned.m16n8k16.row.col.f32.bf16.bf16.f32 "
        "{%0,%1,%2,%3},{%4,%5,%6,%7},{%8,%9},{%0,%1,%2,%3};"
        : "+f"(d[0]), "+f"(d[1]), "+f"(d[2]), "+f"(d[3])
        : "r"(a[0]), "r"(a[1]), "r"(a[2]), "r"(a[3]), "r"(b0), "r"(b1));
}

// ------------------------------------------------------- weight prep (tiny)
__global__ void wprep(const float* __restrict__ Wq, const float* __restrict__ Wk,
                      const float* __restrict__ Wv) {
    int i = blockIdx.x * 256 + threadIdx.x;
    if (i >= NTOT * C_) return;
    int n = i / C_, ck = i % C_;
    const float* W = (n < 64) ? Wq : ((n < 128) ? Wk : Wv);
    float w = W[ck * H_ + (n & 63)];
    __nv_bfloat16 h, l; split1(w, h, l);
    gWhi[i] = h; gWlo[i] = l;
}

// ---------------------------------------------------------------------------
// QKV projection: out[131072,192] = x[131072,384] @ W[384,192]
// split-bf16 3-term mma.sync (fp32-grade accuracy).
// CTA: 128 M x 192 N, BK=32, 512 threads (16 warps, warp tile 32x48).
// ---------------------------------------------------------------------------
#define BKQ 32
#define ASTR 40                         // smem row stride (elements)
#define SM_AH 0
#define SM_AL (128 * ASTR)
#define SM_BH (2 * 128 * ASTR)
#define SM_BL (2 * 128 * ASTR + 192 * ASTR)
#define SMEMQ ((2 * 128 * ASTR + 2 * 192 * ASTR) * 2)   // 51200 B

__global__ __launch_bounds__(512, 1) void qkv_mma(const float* __restrict__ x) {
    extern __shared__ __nv_bfloat16 sm[];
    const int tid  = threadIdx.x;
    const int w    = tid >> 5;
    const int lane = tid & 31;
    const int g    = lane >> 2;        // groupID (row within frag)
    const int tg   = lane & 3;         // thread-in-group (col pair)
    const int wr   = w >> 2;           // warp m index 0..3  -> m off 32*wr
    const int wc   = w & 3;            // warp n index 0..3  -> n off 48*wc
    const size_t row0 = (size_t)blockIdx.x * 128;

    float acc[2][6][4];
#pragma unroll
    for (int mi = 0; mi < 2; mi++)
#pragma unroll
        for (int ni = 0; ni < 6; ni++)
#pragma unroll
            for (int r = 0; r < 4; r++) acc[mi][ni][r] = 0.f;

    // staging registers
    float4 xs[2];
    uint4  ws[3];

    // ---- load chunk 0 into regs ----
    {
        const float* xp = x + row0 * C_;
#pragma unroll
        for (int i = 0; i < 2; i++) {
            int v = tid + i * 512;
            int r = v >> 3, cf = v & 7;
            xs[i] = *(const float4*)(xp + (size_t)r * C_ + cf * 4);
        }
        const uint4* wp = (const uint4*)gWhi;   // rows of 384 bf16 = 48 uint4
        const uint4* lp = (const uint4*)gWlo;
#pragma unroll
        for (int i = 0; i < 3; i++) {
            int u = tid + i * 512;               // 0..1535
            int hi = (u < 768);
            int idx = hi ? u : u - 768;
            int r = idx >> 2, q = idx & 3;       // row 0..191, 16B quarter
            ws[i] = hi ? wp[r * 48 + q] : lp[r * 48 + q];
        }
    }

    const int NCH = C_ / BKQ;   // 12
    for (int c = 0; c < NCH; c++) {
        // ---- store staged regs -> smem (with split for x) ----
#pragma unroll
        for (int i = 0; i < 2; i++) {
            int v = tid + i * 512;
            int r = v >> 3, cf = v & 7;
            __nv_bfloat16 h0, l0, h1, l1, h2, l2, h3, l3;
            split1(xs[i].x, h0, l0); split1(xs[i].y, h1, l1);
            split1(xs[i].z, h2, l2); split1(xs[i].w, h3, l3);
            uint32_t* ph = (uint32_t*)&sm[SM_AH + r * ASTR + cf * 4];
            uint32_t* pl = (uint32_t*)&sm[SM_AL + r * ASTR + cf * 4];
            ph[0] = pack2(h0, h1); ph[1] = pack2(h2, h3);
            pl[0] = pack2(l0, l1); pl[1] = pack2(l2, l3);
        }
#pragma unroll
        for (int i = 0; i < 3; i++) {
            int u = tid + i * 512;
            int hi = (u < 768);
            int idx = hi ? u : u - 768;
            int r = idx >> 2, q = idx & 3;
            uint32_t* p = (uint32_t*)&sm[(hi ? SM_BH : SM_BL) + r * ASTR + q * 8];
            p[0] = ws[i].x; p[1] = ws[i].y; p[2] = ws[i].z; p[3] = ws[i].w;
        }
        __syncthreads();

        // ---- prefetch chunk c+1 into regs ----
        if (c + 1 < NCH) {
            const int c0 = (c + 1) * BKQ;
            const float* xp = x + row0 * C_ + c0;
#pragma unroll
            for (int i = 0; i < 2; i++) {
                int v = tid + i * 512;
                int r = v >> 3, cf = v & 7;
                xs[i] = *(const float4*)(xp + (size_t)r * C_ + cf * 4);
            }
            const uint4* wp = (const uint4*)gWhi;
            const uint4* lp = (const uint4*)gWlo;
            const int qoff = c0 / 8;   // uint4 offset within row
#pragma unroll
            for (int i = 0; i < 3; i++) {
                int u = tid + i * 512;
                int hi = (u < 768);
                int idx = hi ? u : u - 768;
                int r = idx >> 2, q = idx & 3;
                ws[i] = hi ? wp[r * 48 + qoff + q] : lp[r * 48 + qoff + q];
            }
        }

        // ---- compute: 2 k16 steps ----
#pragma unroll
        for (int ks = 0; ks < 2; ks++) {
            const int k0 = ks * 16;
            uint32_t ah[2][4], al[2][4];
#pragma unroll
            for (int mi = 0; mi < 2; mi++) {
                int rb = wr * 32 + mi * 16 + g;
                ah[mi][0] = *(const uint32_t*)&sm[SM_AH + rb * ASTR + k0 + tg * 2];
                ah[mi][1] = *(const uint32_t*)&sm[SM_AH + (rb + 8) * ASTR + k0 + tg * 2];
                ah[mi][2] = *(const uint32_t*)&sm[SM_AH + rb * ASTR + k0 + 8 + tg * 2];
                ah[mi][3] = *(const uint32_t*)&sm[SM_AH + (rb + 8) * ASTR + k0 + 8 + tg * 2];
                al[mi][0] = *(const uint32_t*)&sm[SM_AL + rb * ASTR + k0 + tg * 2];
                al[mi][1] = *(const uint32_t*)&sm[SM_AL + (rb + 8) * ASTR + k0 + tg * 2];
                al[mi][2] = *(const uint32_t*)&sm[SM_AL + rb * ASTR + k0 + 8 + tg * 2];
                al[mi][3] = *(const uint32_t*)&sm[SM_AL + (rb + 8) * ASTR + k0 + 8 + tg * 2];
            }
#pragma unroll
            for (int ni = 0; ni < 6; ni++) {
                int n = wc * 48 + ni * 8 + g;
                uint32_t bh0 = *(const uint32_t*)&sm[SM_BH + n * ASTR + k0 + tg * 2];
                uint32_t bh1 = *(const uint32_t*)&sm[SM_BH + n * ASTR + k0 + 8 + tg * 2];
                uint32_t bl0 = *(const uint32_t*)&sm[SM_BL + n * ASTR + k0 + tg * 2];
                uint32_t bl1 = *(const uint32_t*)&sm[SM_BL + n * ASTR + k0 + 8 + tg * 2];
#pragma unroll
                for (int mi = 0; mi < 2; mi++) {
                    mma16816(acc[mi][ni], ah[mi], bh0, bh1);
                    mma16816(acc[mi][ni], al[mi], bh0, bh1);
                    mma16816(acc[mi][ni], ah[mi], bl0, bl1);
                }
            }
        }
        __syncthreads();
    }

    // ---- epilogue ----
#pragma unroll
    for (int mi = 0; mi < 2; mi++) {
        size_t m0 = row0 + wr * 32 + mi * 16 + g;
#pragma unroll
        for (int ni = 0; ni < 6; ni++) {
            int n = wc * 48 + ni * 8 + tg * 2;
            float* o = (n < 64) ? g_q : ((n < 128) ? g_k : g_v);
            int col = n & 63;
            *(float2*)&o[m0 * H_ + col] =
                make_float2(acc[mi][ni][0], acc[mi][ni][1]);
            *(float2*)&o[(m0 + 8) * H_ + col] =
                make_float2(acc[mi][ni][2], acc[mi][ni][3]);
        }
    }
}

// ---------------------------------------------------------------------------
// Kernel 2: causal attention (unchanged fp32 baseline).
// ---------------------------------------------------------------------------
#define SSTR 260
#define KSTR 68
#define SMEM2 ((2 * 64 * KSTR + 64 * SSTR) * 4)

__global__ __launch_bounds__(256) void attn(float* __restrict__ out) {
    extern __shared__ float smf[];
    float* sQ  = smf;
    float* sKV = smf + 64 * KSTR;
    float* sS  = smf + 2 * 64 * KSTR;

    const int b    = blockIdx.x;
    const int qt   = blockIdx.y;
    const int q0   = qt * 64;
    const int tid  = threadIdx.x;
    const int tx   = tid & 15;
    const int ty   = tid >> 4;
    const int lane = tid & 31;
    const int wid  = tid >> 5;

    const float* Q = g_q + ((size_t)b * T_ + q0) * H_;
    const float* K = g_k + (size_t)b * T_ * H_;
    const float* V = g_v + (size_t)b * T_ * H_;

#pragma unroll
    for (int i = 0; i < 4; i++) {
        int v  = tid + i * 256;
        int r  = v >> 4;
        int cf = v & 15;
        float4 a = *(const float4*)(Q + r * H_ + cf * 4);
        sQ[(cf * 4 + 0) * KSTR + r] = a.x;
        sQ[(cf * 4 + 1) * KSTR + r] = a.y;
        sQ[(cf * 4 + 2) * KSTR + r] = a.z;
        sQ[(cf * 4 + 3) * KSTR + r] = a.w;
    }

    for (int kt = 0; kt <= qt; kt++) {
        __syncthreads();
#pragma unroll
        for (int i = 0; i < 4; i++) {
            int v  = tid + i * 256;
            int r  = v >> 4;
            int cf = v & 15;
            float4 a = *(const float4*)(K + (kt * 64 + r) * H_ + cf * 4);
            sKV[(cf * 4 + 0) * KSTR + r] = a.x;
            sKV[(cf * 4 + 1) * KSTR + r] = a.y;
            sKV[(cf * 4 + 2) * KSTR + r] = a.z;
            sKV[(cf * 4 + 3) * KSTR + r] = a.w;
        }
        __syncthreads();

        float s[4][4];
#pragma unroll
        for (int i = 0; i < 4; i++)
#pragma unroll
            for (int j = 0; j < 4; j++) s[i][j] = 0.f;

#pragma unroll
        for (int kk = 0; kk < 64; kk++) {
            float4 a = *(const float4*)(&sQ[kk * KSTR + ty * 4]);
            float4 bK = *(const float4*)(&sKV[kk * KSTR + tx * 4]);
            float av[4] = {a.x, a.y, a.z, a.w};
            float bv[4] = {bK.x, bK.y, bK.z, bK.w};
#pragma unroll
            for (int i = 0; i < 4; i++)
#pragma unroll
                for (int j = 0; j < 4; j++) s[i][j] += av[i] * bv[j];
        }

#pragma unroll
        for (int i = 0; i < 4; i++) {
            int gq = q0 + ty * 4 + i;
#pragma unroll
            for (int j = 0; j < 4; j++) {
                int gk = kt * 64 + tx * 4 + j;
                sS[(ty * 4 + i) * SSTR + gk] =
                    (gk <= gq) ? s[i][j] * 0.125f : -1e30f;
            }
        }
    }
    __syncthreads();

    const int nk = (qt + 1) * 64;
    for (int r = wid; r < 64; r += 8) {
        float m = -1e30f;
        for (int c = lane; c < nk; c += 32) m = fmaxf(m, sS[r * SSTR + c]);
#pragma unroll
        for (int o = 16; o; o >>= 1) m = fmaxf(m, __shfl_xor_sync(0xFFFFFFFFu, m, o));
        float sum = 0.f;
        for (int c = lane; c < nk; c += 32) {
            float e = __expf(sS[r * SSTR + c] - m);
            sS[r * SSTR + c] = e;
            sum += e;
        }
#pragma unroll
        for (int o = 16; o; o >>= 1) sum += __shfl_xor_sync(0xFFFFFFFFu, sum, o);
        float inv = 1.f / sum;
        for (int c = lane; c < nk; c += 32) sS[r * SSTR + c] *= inv;
    }
    __syncthreads();

    float o[4][4];
#pragma unroll
    for (int i = 0; i < 4; i++)
#pragma unroll
        for (int j = 0; j < 4; j++) o[i][j] = 0.f;

    for (int kt = 0; kt <= qt; kt++) {
#pragma unroll
        for (int i = 0; i < 4; i++) {
            int v  = tid + i * 256;
            int r  = v >> 4;
            int cf = v & 15;
            *(float4*)(&sKV[r * KSTR + cf * 4]) =
                *(const float4*)(V + (kt * 64 + r) * H_ + cf * 4);
        }
        __syncthreads();
#pragma unroll
        for (int kk = 0; kk < 64; kk++) {
            float4 bV = *(const float4*)(&sKV[kk * KSTR + tx * 4]);
            float bv[4] = {bV.x, bV.y, bV.z, bV.w};
            float av[4];
#pragma unroll
            for (int i = 0; i < 4; i++) av[i] = sS[(ty * 4 + i) * SSTR + kt * 64 + kk];
#pragma unroll
            for (int i = 0; i < 4; i++)
#pragma unroll
                for (int j = 0; j < 4; j++) o[i][j] += av[i] * bv[j];
        }
        __syncthreads();
    }

#pragma unroll
    for (int i = 0; i < 4; i++) {
        float4 ov = make_float4(o[i][0], o[i][1], o[i][2], o[i][3]);
        *(float4*)(out + ((size_t)b * T_ + q0 + ty * 4 + i) * H_ + tx * 4) = ov;
    }
}

// ---------------------------------------------------------------------------
extern "C" void kernel_launch(void* const* d_in, const int* in_sizes, int n_in,
                              void* d_out, int out_size) {
    const float* x  = (const float*)d_in[0];
    const float* Wq = (const float*)d_in[1];
    const float* Wk = (const float*)d_in[2];
    const float* Wv = (const float*)d_in[3];
    float* out = (float*)d_out;
    (void)in_sizes; (void)n_in; (void)out_size;

    cudaFuncSetAttribute(qkv_mma, cudaFuncAttributeMaxDynamicSharedMemorySize, SMEMQ);
    cudaFuncSetAttribute(attn, cudaFuncAttributeMaxDynamicSharedMemorySize, SMEM2);

    wprep<<<(NTOT * C_ + 255) / 256, 256>>>(Wq, Wk, Wv);
    qkv_mma<<<(B_ * T_) / 128, 512, SMEMQ>>>(x);
    attn<<<dim3(B_, T_ / 64), 256, SMEM2>>>(out);
}

// round 4
// speedup vs baseline: 1.8453x; 1.1908x over previous
#include <cuda_runtime.h>
#include <cuda_bf16.h>
#include <cstdint>

#define B_ 512
#define T_ 256
#define C_ 384
#define H_ 64
#define NTOT 192

// split-bf16 q/k planes, row-major [tok][dim]
__device__ __align__(16) __nv_bfloat16 g_qh[B_ * T_ * H_];
__device__ __align__(16) __nv_bfloat16 g_ql[B_ * T_ * H_];
__device__ __align__(16) __nv_bfloat16 g_kh[B_ * T_ * H_];
__device__ __align__(16) __nv_bfloat16 g_kl[B_ * T_ * H_];
// split-bf16 v planes, transposed per batch [b][dim][tok]
__device__ __align__(16) __nv_bfloat16 g_vh[B_ * T_ * H_];
__device__ __align__(16) __nv_bfloat16 g_vl[B_ * T_ * H_];
// pre-split weights, K-major [n(q|k|v)][384]
__device__ __align__(16) __nv_bfloat16 gWhi[NTOT * C_];
__device__ __align__(16) __nv_bfloat16 gWlo[NTOT * C_];

__device__ __forceinline__ void split1(float v, __nv_bfloat16& h, __nv_bfloat16& l) {
    h = __float2bfloat16(v);
    l = __float2bfloat16(v - __bfloat162float(h));
}
__device__ __forceinline__ uint32_t pack2(__nv_bfloat16 a, __nv_bfloat16 b) {
    __nv_bfloat162 t = __halves2bfloat162(a, b);
    uint32_t u; memcpy(&u, &t, 4); return u;
}
__device__ __forceinline__ void mma16816(float* d, const uint32_t* a,
                                         uint32_t b0, uint32_t b1) {
    asm volatile(
        "mma.sync.aligned.m16n8k16.row.col.f32.bf16.bf16.f32 "
        "{%0,%1,%2,%3},{%4,%5,%6,%7},{%8,%9},{%0,%1,%2,%3};"
        : "+f"(d[0]), "+f"(d[1]), "+f"(d[2]), "+f"(d[3])
        : "r"(a[0]), "r"(a[1]), "r"(a[2]), "r"(a[3]), "r"(b0), "r"(b1));
}

// ------------------------------------------------------- weight prep (tiny)
__global__ void wprep(const float* __restrict__ Wq, const float* __restrict__ Wk,
                      const float* __restrict__ Wv) {
    int i = blockIdx.x * 256 + threadIdx.x;
    if (i >= NTOT * C_) return;
    int n = i / C_, ck = i % C_;
    const float* W = (n < 64) ? Wq : ((n < 128) ? Wk : Wv);
    float w = W[ck * H_ + (n & 63)];
    __nv_bfloat16 h, l; split1(w, h, l);
    gWhi[i] = h; gWlo[i] = l;
}

// ---------------------------------------------------------------------------
// QKV projection: [131072,192] = x[131072,384] @ W[384,192], split-bf16 mma.
// Epilogue writes split hi/lo planes (q,k row-major; v transposed).
// ---------------------------------------------------------------------------
#define BKQ 32
#define ASTR 40
#define SM_AH 0
#define SM_AL (128 * ASTR)
#define SM_BH (2 * 128 * ASTR)
#define SM_BL (2 * 128 * ASTR + 192 * ASTR)
#define SMEMQ ((2 * 128 * ASTR + 2 * 192 * ASTR) * 2)

__global__ __launch_bounds__(512, 1) void qkv_mma(const float* __restrict__ x) {
    extern __shared__ __nv_bfloat16 sm[];
    const int tid  = threadIdx.x;
    const int w    = tid >> 5;
    const int lane = tid & 31;
    const int g    = lane >> 2;
    const int tg   = lane & 3;
    const int wr   = w >> 2;
    const int wc   = w & 3;
    const size_t row0 = (size_t)blockIdx.x * 128;

    float acc[2][6][4];
#pragma unroll
    for (int mi = 0; mi < 2; mi++)
#pragma unroll
        for (int ni = 0; ni < 6; ni++)
#pragma unroll
            for (int r = 0; r < 4; r++) acc[mi][ni][r] = 0.f;

    float4 xs[2];
    uint4  ws[3];
    {
        const float* xp = x + row0 * C_;
#pragma unroll
        for (int i = 0; i < 2; i++) {
            int v = tid + i * 512;
            int r = v >> 3, cf = v & 7;
            xs[i] = *(const float4*)(xp + (size_t)r * C_ + cf * 4);
        }
        const uint4* wp = (const uint4*)gWhi;
        const uint4* lp = (const uint4*)gWlo;
#pragma unroll
        for (int i = 0; i < 3; i++) {
            int u = tid + i * 512;
            int hi = (u < 768);
            int idx = hi ? u : u - 768;
            int r = idx >> 2, q = idx & 3;
            ws[i] = hi ? wp[r * 48 + q] : lp[r * 48 + q];
        }
    }

    const int NCH = C_ / BKQ;
    for (int c = 0; c < NCH; c++) {
#pragma unroll
        for (int i = 0; i < 2; i++) {
            int v = tid + i * 512;
            int r = v >> 3, cf = v & 7;
            __nv_bfloat16 h0, l0, h1, l1, h2, l2, h3, l3;
            split1(xs[i].x, h0, l0); split1(xs[i].y, h1, l1);
            split1(xs[i].z, h2, l2); split1(xs[i].w, h3, l3);
            uint32_t* ph = (uint32_t*)&sm[SM_AH + r * ASTR + cf * 4];
            uint32_t* pl = (uint32_t*)&sm[SM_AL + r * ASTR + cf * 4];
            ph[0] = pack2(h0, h1); ph[1] = pack2(h2, h3);
            pl[0] = pack2(l0, l1); pl[1] = pack2(l2, l3);
        }
#pragma unroll
        for (int i = 0; i < 3; i++) {
            int u = tid + i * 512;
            int hi = (u < 768);
            int idx = hi ? u : u - 768;
            int r = idx >> 2, q = idx & 3;
            uint32_t* p = (uint32_t*)&sm[(hi ? SM_BH : SM_BL) + r * ASTR + q * 8];
            p[0] = ws[i].x; p[1] = ws[i].y; p[2] = ws[i].z; p[3] = ws[i].w;
        }
        __syncthreads();

        if (c + 1 < NCH) {
            const int c0 = (c + 1) * BKQ;
            const float* xp = x + row0 * C_ + c0;
#pragma unroll
            for (int i = 0; i < 2; i++) {
                int v = tid + i * 512;
                int r = v >> 3, cf = v & 7;
                xs[i] = *(const float4*)(xp + (size_t)r * C_ + cf * 4);
            }
            const uint4* wp = (const uint4*)gWhi;
            const uint4* lp = (const uint4*)gWlo;
            const int qoff = c0 / 8;
#pragma unroll
            for (int i = 0; i < 3; i++) {
                int u = tid + i * 512;
                int hi = (u < 768);
                int idx = hi ? u : u - 768;
                int r = idx >> 2, q = idx & 3;
                ws[i] = hi ? wp[r * 48 + qoff + q] : lp[r * 48 + qoff + q];
            }
        }

#pragma unroll
        for (int ks = 0; ks < 2; ks++) {
            const int k0 = ks * 16;
            uint32_t ah[2][4], al[2][4];
#pragma unroll
            for (int mi = 0; mi < 2; mi++) {
                int rb = wr * 32 + mi * 16 + g;
                ah[mi][0] = *(const uint32_t*)&sm[SM_AH + rb * ASTR + k0 + tg * 2];
                ah[mi][1] = *(const uint32_t*)&sm[SM_AH + (rb + 8) * ASTR + k0 + tg * 2];
                ah[mi][2] = *(const uint32_t*)&sm[SM_AH + rb * ASTR + k0 + 8 + tg * 2];
                ah[mi][3] = *(const uint32_t*)&sm[SM_AH + (rb + 8) * ASTR + k0 + 8 + tg * 2];
                al[mi][0] = *(const uint32_t*)&sm[SM_AL + rb * ASTR + k0 + tg * 2];
                al[mi][1] = *(const uint32_t*)&sm[SM_AL + (rb + 8) * ASTR + k0 + tg * 2];
                al[mi][2] = *(const uint32_t*)&sm[SM_AL + rb * ASTR + k0 + 8 + tg * 2];
                al[mi][3] = *(const uint32_t*)&sm[SM_AL + (rb + 8) * ASTR + k0 + 8 + tg * 2];
            }
#pragma unroll
            for (int ni = 0; ni < 6; ni++) {
                int n = wc * 48 + ni * 8 + g;
                uint32_t bh0 = *(const uint32_t*)&sm[SM_BH + n * ASTR + k0 + tg * 2];
                uint32_t bh1 = *(const uint32_t*)&sm[SM_BH + n * ASTR + k0 + 8 + tg * 2];
                uint32_t bl0 = *(const uint32_t*)&sm[SM_BL + n * ASTR + k0 + tg * 2];
                uint32_t bl1 = *(const uint32_t*)&sm[SM_BL + n * ASTR + k0 + 8 + tg * 2];
#pragma unroll
                for (int mi = 0; mi < 2; mi++) {
                    mma16816(acc[mi][ni], ah[mi], bh0, bh1);
                    mma16816(acc[mi][ni], al[mi], bh0, bh1);
                    mma16816(acc[mi][ni], ah[mi], bl0, bl1);
                }
            }
        }
        __syncthreads();
    }

    // ---- epilogue: split fp32 acc -> bf16 hi/lo planes ----
#pragma unroll
    for (int mi = 0; mi < 2; mi++) {
        size_t m0 = row0 + wr * 32 + mi * 16 + g;
#pragma unroll
        for (int ni = 0; ni < 6; ni++) {
            int n = wc * 48 + ni * 8 + tg * 2;
            __nv_bfloat16 h0, l0, h1, l1, h2, l2, h3, l3;
            split1(acc[mi][ni][0], h0, l0); split1(acc[mi][ni][1], h1, l1);
            split1(acc[mi][ni][2], h2, l2); split1(acc[mi][ni][3], h3, l3);
            if (n < 128) {
                __nv_bfloat16* ph = (n < 64) ? g_qh : g_kh;
                __nv_bfloat16* pl = (n < 64) ? g_ql : g_kl;
                int col = n & 63;
                ((uint32_t*)ph)[(m0 * H_ + col) >> 1]       = pack2(h0, h1);
                ((uint32_t*)ph)[((m0 + 8) * H_ + col) >> 1] = pack2(h2, h3);
                ((uint32_t*)pl)[(m0 * H_ + col) >> 1]       = pack2(l0, l1);
                ((uint32_t*)pl)[((m0 + 8) * H_ + col) >> 1] = pack2(l2, l3);
            } else {
                int col = n - 128;
                size_t bb = m0 >> 8;
                int t = (int)(m0 & 255);
                size_t base = bb * (size_t)(H_ * T_);
                g_vh[base + col * T_ + t]           = h0;
                g_vh[base + (col + 1) * T_ + t]     = h1;
                g_vh[base + col * T_ + t + 8]       = h2;
                g_vh[base + (col + 1) * T_ + t + 8] = h3;
                g_vl[base + col * T_ + t]           = l0;
                g_vl[base + (col + 1) * T_ + t]     = l1;
                g_vl[base + col * T_ + t + 8]       = l2;
                g_vl[base + (col + 1) * T_ + t + 8] = l3;
            }
        }
    }
}

// ---------------------------------------------------------------------------
// Attention v2: tensor-core QK^T and PV (split-bf16 3-term), fp32 softmax.
// CTA = (batch, 64-query tile), 256 threads = 8 warps (4 m x 2 n tiles).
// ---------------------------------------------------------------------------
#define SSTR 260
#define KST 72
#define SMEM2 (64 * SSTR * 4 + 2 * 64 * KST * 2)   // 84992 B

__global__ __launch_bounds__(256) void attn(float* __restrict__ out) {
    extern __shared__ char smc[];
    float* sS = (float*)smc;
    __nv_bfloat16* sPH = (__nv_bfloat16*)(smc + 64 * SSTR * 4);  // K/V hi plane
    __nv_bfloat16* sPL = sPH + 64 * KST;                          // K/V lo plane

    const int b    = blockIdx.x;
    const int qt   = blockIdx.y;
    const int q0   = qt * 64;
    const int tid  = threadIdx.x;
    const int lane = tid & 31;
    const int w    = tid >> 5;
    const int g    = lane >> 2;
    const int tg   = lane & 3;
    const int wm   = w >> 1;       // 0..3
    const int wn   = w & 1;        // 0..1
    const int rowm = wm * 16 + g;  // row within 64-q tile (plus +8 variant)

    // ---- Q fragments (hi/lo), loaded once from gmem ----
    uint32_t qh[4][4], ql[4][4];
    {
        const size_t rb = (size_t)b * T_ + q0 + wm * 16;
        const uint32_t* QH = (const uint32_t*)g_qh;
        const uint32_t* QL = (const uint32_t*)g_ql;
#pragma unroll
        for (int c = 0; c < 4; c++) {
            int d = c * 16 + tg * 2;
            qh[c][0] = QH[((rb + g) * H_ + d) >> 1];
            qh[c][1] = QH[((rb + g + 8) * H_ + d) >> 1];
            qh[c][2] = QH[((rb + g) * H_ + d + 8) >> 1];
            qh[c][3] = QH[((rb + g + 8) * H_ + d + 8) >> 1];
            ql[c][0] = QL[((rb + g) * H_ + d) >> 1];
            ql[c][1] = QL[((rb + g + 8) * H_ + d) >> 1];
            ql[c][2] = QL[((rb + g) * H_ + d + 8) >> 1];
            ql[c][3] = QL[((rb + g + 8) * H_ + d + 8) >> 1];
        }
    }

    // ---- Phase A: S = mask(QK^T * 0.125) into sS ----
    for (int kt = 0; kt <= qt; kt++) {
        __syncthreads();
        {   // load K tile hi/lo: 64 keys x 64 dims
            const uint4* KH = (const uint4*)g_kh;
            const uint4* KL = (const uint4*)g_kl;
#pragma unroll
            for (int i = 0; i < 2; i++) {
                int v = tid + i * 256;
                int r = v >> 3, c8 = v & 7;
                size_t src = ((size_t)b * T_ + kt * 64 + r) * (H_ / 8) + c8;
                *(uint4*)&sPH[r * KST + c8 * 8] = KH[src];
                *(uint4*)&sPL[r * KST + c8 * 8] = KL[src];
            }
        }
        __syncthreads();

        float sacc[4][4];
#pragma unroll
        for (int f = 0; f < 4; f++)
#pragma unroll
            for (int r = 0; r < 4; r++) sacc[f][r] = 0.f;

#pragma unroll
        for (int c = 0; c < 4; c++) {
            const int k0 = c * 16 + tg * 2;
#pragma unroll
            for (int f = 0; f < 4; f++) {
                int n = wn * 32 + f * 8 + g;
                uint32_t bh0 = *(const uint32_t*)&sPH[n * KST + k0];
                uint32_t bh1 = *(const uint32_t*)&sPH[n * KST + k0 + 8];
                uint32_t bl0 = *(const uint32_t*)&sPL[n * KST + k0];
                uint32_t bl1 = *(const uint32_t*)&sPL[n * KST + k0 + 8];
                mma16816(sacc[f], qh[c], bh0, bh1);
                mma16816(sacc[f], ql[c], bh0, bh1);
                mma16816(sacc[f], qh[c], bl0, bl1);
            }
        }

        // mask + scale + store to sS
        const int gq0 = q0 + rowm;
        const int gq1 = gq0 + 8;
#pragma unroll
        for (int f = 0; f < 4; f++) {
            int colb = kt * 64 + wn * 32 + f * 8 + tg * 2;
            float2 d0 = make_float2(
                (colb     <= gq0) ? sacc[f][0] * 0.125f : -1e30f,
                (colb + 1 <= gq0) ? sacc[f][1] * 0.125f : -1e30f);
            float2 d1 = make_float2(
                (colb     <= gq1) ? sacc[f][2] * 0.125f : -1e30f,
                (colb + 1 <= gq1) ? sacc[f][3] * 0.125f : -1e30f);
            *(float2*)&sS[rowm * SSTR + colb]       = d0;
            *(float2*)&sS[(rowm + 8) * SSTR + colb] = d1;
        }
    }
    __syncthreads();

    // ---- Phase B: row softmax ----
    const int nk = (qt + 1) * 64;
    for (int r = w; r < 64; r += 8) {
        float m = -1e30f;
        for (int c = lane; c < nk; c += 32) m = fmaxf(m, sS[r * SSTR + c]);
#pragma unroll
        for (int o = 16; o; o >>= 1) m = fmaxf(m, __shfl_xor_sync(0xFFFFFFFFu, m, o));
        float sum = 0.f;
        for (int c = lane; c < nk; c += 32) {
            float e = __expf(sS[r * SSTR + c] - m);
            sS[r * SSTR + c] = e;
            sum += e;
        }
#pragma unroll
        for (int o = 16; o; o >>= 1) sum += __shfl_xor_sync(0xFFFFFFFFu, sum, o);
        float inv = 1.f / sum;
        for (int c = lane; c < nk; c += 32) sS[r * SSTR + c] *= inv;
    }

    // ---- Phase C: O = P V (split-bf16 3-term) ----
    float oacc[4][4];
#pragma unroll
    for (int f = 0; f < 4; f++)
#pragma unroll
        for (int r = 0; r < 4; r++) oacc[f][r] = 0.f;

    for (int kt = 0; kt <= qt; kt++) {
        __syncthreads();
        {   // load V tile hi/lo (transposed layout [dim][tok]): 64 dims x 64 keys
            const uint4* VH = (const uint4*)g_vh;
            const uint4* VL = (const uint4*)g_vl;
#pragma unroll
            for (int i = 0; i < 2; i++) {
                int v = tid + i * 256;
                int r = v >> 3, c8 = v & 7;
                size_t src = ((size_t)b * (H_ * T_) + (size_t)r * T_ + kt * 64) / 8 + c8;
                *(uint4*)&sPH[r * KST + c8 * 8] = VH[src];
                *(uint4*)&sPL[r * KST + c8 * 8] = VL[src];
            }
        }
        __syncthreads();

#pragma unroll
        for (int c = 0; c < 4; c++) {
            // P fragments from sS, split to bf16 hi/lo
            uint32_t ph[4], pl[4];
            {
                int colb = kt * 64 + c * 16 + tg * 2;
                float2 p0 = *(const float2*)&sS[rowm * SSTR + colb];
                float2 p1 = *(const float2*)&sS[(rowm + 8) * SSTR + colb];
                float2 p2 = *(const float2*)&sS[rowm * SSTR + colb + 8];
                float2 p3 = *(const float2*)&sS[(rowm + 8) * SSTR + colb + 8];
                __nv_bfloat16 h0, l0, h1, l1;
                split1(p0.x, h0, l0); split1(p0.y, h1, l1);
                ph[0] = pack2(h0, h1); pl[0] = pack2(l0, l1);
                split1(p1.x, h0, l0); split1(p1.y, h1, l1);
                ph[1] = pack2(h0, h1); pl[1] = pack2(l0, l1);
                split1(p2.x, h0, l0); split1(p2.y, h1, l1);
                ph[2] = pack2(h0, h1); pl[2] = pack2(l0, l1);
                split1(p3.x, h0, l0); split1(p3.y, h1, l1);
                ph[3] = pack2(h0, h1); pl[3] = pack2(l0, l1);
            }
            const int k0 = c * 16 + tg * 2;
#pragma unroll
            for (int f = 0; f < 4; f++) {
                int n = wn * 32 + f * 8 + g;       // output dim
                uint32_t vh0 = *(const uint32_t*)&sPH[n * KST + k0];
                uint32_t vh1 = *(const uint32_t*)&sPH[n * KST + k0 + 8];
                uint32_t vl0 = *(const uint32_t*)&sPL[n * KST + k0];
                uint32_t vl1 = *(const uint32_t*)&sPL[n * KST + k0 + 8];
                mma16816(oacc[f], ph, vh0, vh1);
                mma16816(oacc[f], pl, vh0, vh1);
                mma16816(oacc[f], ph, vl0, vl1);
            }
        }
    }

    // ---- epilogue: fp32 out ----
    {
        size_t r0 = (size_t)b * T_ + q0 + rowm;
#pragma unroll
        for (int f = 0; f < 4; f++) {
            int col = wn * 32 + f * 8 + tg * 2;
            *(float2*)&out[r0 * H_ + col]       = make_float2(oacc[f][0], oacc[f][1]);
            *(float2*)&out[(r0 + 8) * H_ + col] = make_float2(oacc[f][2], oacc[f][3]);
        }
    }
}

// ---------------------------------------------------------------------------
extern "C" void kernel_launch(void* const* d_in, const int* in_sizes, int n_in,
                              void* d_out, int out_size) {
    const float* x  = (const float*)d_in[0];
    const float* Wq = (const float*)d_in[1];
    const float* Wk = (const float*)d_in[2];
    const float* Wv = (const float*)d_in[3];
    float* out = (float*)d_out;
    (void)in_sizes; (void)n_in; (void)out_size;

    cudaFuncSetAttribute(qkv_mma, cudaFuncAttributeMaxDynamicSharedMemorySize, SMEMQ);
    cudaFuncSetAttribute(attn, cudaFuncAttributeMaxDynamicSharedMemorySize, SMEM2);

    wprep<<<(NTOT * C_ + 255) / 256, 256>>>(Wq, Wk, Wv);
    qkv_mma<<<(B_ * T_) / 128, 512, SMEMQ>>>(x);
    attn<<<dim3(B_, T_ / 64), 256, SMEM2>>>(out);
}

// round 6
// speedup vs baseline: 2.0421x; 1.1066x over previous
#include <cuda_runtime.h>
#include <cuda_bf16.h>
#include <cstdint>

#define B_ 512
#define T_ 256
#define C_ 384
#define H_ 64
#define NTOT 192

// split-bf16 q/k planes, row-major [tok][dim]
__device__ __align__(16) __nv_bfloat16 g_qh[B_ * T_ * H_];
__device__ __align__(16) __nv_bfloat16 g_ql[B_ * T_ * H_];
__device__ __align__(16) __nv_bfloat16 g_kh[B_ * T_ * H_];
__device__ __align__(16) __nv_bfloat16 g_kl[B_ * T_ * H_];
// split-bf16 v planes, transposed per batch [b][dim][tok]
__device__ __align__(16) __nv_bfloat16 g_vh[B_ * T_ * H_];
__device__ __align__(16) __nv_bfloat16 g_vl[B_ * T_ * H_];
// pre-split weights, K-major [n(q|k|v)][384]
__device__ __align__(16) __nv_bfloat16 gWhi[NTOT * C_];
__device__ __align__(16) __nv_bfloat16 gWlo[NTOT * C_];

__device__ __forceinline__ void split1(float v, __nv_bfloat16& h, __nv_bfloat16& l) {
    h = __float2bfloat16(v);
    l = __float2bfloat16(v - __bfloat162float(h));
}
__device__ __forceinline__ uint32_t pack2(__nv_bfloat16 a, __nv_bfloat16 b) {
    __nv_bfloat162 t = __halves2bfloat162(a, b);
    uint32_t u; memcpy(&u, &t, 4); return u;
}
__device__ __forceinline__ void mma16816(float* d, const uint32_t* a,
                                         uint32_t b0, uint32_t b1) {
    asm volatile(
        "mma.sync.aligned.m16n8k16.row.col.f32.bf16.bf16.f32 "
        "{%0,%1,%2,%3},{%4,%5,%6,%7},{%8,%9},{%0,%1,%2,%3};"
        : "+f"(d[0]), "+f"(d[1]), "+f"(d[2]), "+f"(d[3])
        : "r"(a[0]), "r"(a[1]), "r"(a[2]), "r"(a[3]), "r"(b0), "r"(b1));
}
__device__ __forceinline__ void ldm4(uint32_t& r0, uint32_t& r1, uint32_t& r2,
                                     uint32_t& r3, uint32_t addr) {
    asm volatile("ldmatrix.sync.aligned.m8n8.x4.shared.b16 {%0,%1,%2,%3},[%4];"
                 : "=r"(r0), "=r"(r1), "=r"(r2), "=r"(r3) : "r"(addr));
}
__device__ __forceinline__ uint32_t smem_u32(const void* p) {
    uint32_t a;
    asm("{ .reg .u64 t; cvta.to.shared.u64 t, %1; cvt.u32.u64 %0, t; }"
        : "=r"(a) : "l"(p));
    return a;
}

// ------------------------------------------------------- weight prep (tiny)
__global__ void wprep(const float* __restrict__ Wq, const float* __restrict__ Wk,
                      const float* __restrict__ Wv) {
    int i = blockIdx.x * 256 + threadIdx.x;
    if (i >= NTOT * C_) return;
    int n = i / C_, ck = i % C_;
    const float* W = (n < 64) ? Wq : ((n < 128) ? Wk : Wv);
    float w = W[ck * H_ + (n & 63)];
    __nv_bfloat16 h, l; split1(w, h, l);
    gWhi[i] = h; gWlo[i] = l;
}

// ---------------------------------------------------------------------------
// QKV projection: split-bf16 3-term mma.sync.
// ---------------------------------------------------------------------------
#define BKQ 32
#define ASTR 40
#define SM_AH 0
#define SM_AL (128 * ASTR)
#define SM_BH (2 * 128 * ASTR)
#define SM_BL (2 * 128 * ASTR + 192 * ASTR)
#define SMEMQ ((2 * 128 * ASTR + 2 * 192 * ASTR) * 2)

__global__ __launch_bounds__(512, 1) void qkv_mma(const float* __restrict__ x) {
    extern __shared__ __nv_bfloat16 sm[];
    const int tid  = threadIdx.x;
    const int w    = tid >> 5;
    const int lane = tid & 31;
    const int g    = lane >> 2;
    const int tg   = lane & 3;
    const int wr   = w >> 2;
    const int wc   = w & 3;
    const size_t row0 = (size_t)blockIdx.x * 128;

    float acc[2][6][4];
#pragma unroll
    for (int mi = 0; mi < 2; mi++)
#pragma unroll
        for (int ni = 0; ni < 6; ni++)
#pragma unroll
            for (int r = 0; r < 4; r++) acc[mi][ni][r] = 0.f;

    float4 xs[2];
    uint4  ws[3];
    {
        const float* xp = x + row0 * C_;
#pragma unroll
        for (int i = 0; i < 2; i++) {
            int v = tid + i * 512;
            int r = v >> 3, cf = v & 7;
            xs[i] = *(const float4*)(xp + (size_t)r * C_ + cf * 4);
        }
        const uint4* wp = (const uint4*)gWhi;
        const uint4* lp = (const uint4*)gWlo;
#pragma unroll
        for (int i = 0; i < 3; i++) {
            int u = tid + i * 512;
            int hi = (u < 768);
            int idx = hi ? u : u - 768;
            int r = idx >> 2, q = idx & 3;
            ws[i] = hi ? wp[r * 48 + q] : lp[r * 48 + q];
        }
    }

    const int NCH = C_ / BKQ;
    for (int c = 0; c < NCH; c++) {
#pragma unroll
        for (int i = 0; i < 2; i++) {
            int v = tid + i * 512;
            int r = v >> 3, cf = v & 7;
            __nv_bfloat16 h0, l0, h1, l1, h2, l2, h3, l3;
            split1(xs[i].x, h0, l0); split1(xs[i].y, h1, l1);
            split1(xs[i].z, h2, l2); split1(xs[i].w, h3, l3);
            uint32_t* ph = (uint32_t*)&sm[SM_AH + r * ASTR + cf * 4];
            uint32_t* pl = (uint32_t*)&sm[SM_AL + r * ASTR + cf * 4];
            ph[0] = pack2(h0, h1); ph[1] = pack2(h2, h3);
            pl[0] = pack2(l0, l1); pl[1] = pack2(l2, l3);
        }
#pragma unroll
        for (int i = 0; i < 3; i++) {
            int u = tid + i * 512;
            int hi = (u < 768);
            int idx = hi ? u : u - 768;
            int r = idx >> 2, q = idx & 3;
            uint32_t* p = (uint32_t*)&sm[(hi ? SM_BH : SM_BL) + r * ASTR + q * 8];
            p[0] = ws[i].x; p[1] = ws[i].y; p[2] = ws[i].z; p[3] = ws[i].w;
        }
        __syncthreads();

        if (c + 1 < NCH) {
            const int c0 = (c + 1) * BKQ;
            const float* xp = x + row0 * C_ + c0;
#pragma unroll
            for (int i = 0; i < 2; i++) {
                int v = tid + i * 512;
                int r = v >> 3, cf = v & 7;
                xs[i] = *(const float4*)(xp + (size_t)r * C_ + cf * 4);
            }
            const uint4* wp = (const uint4*)gWhi;
            const uint4* lp = (const uint4*)gWlo;
            const int qoff = c0 / 8;
#pragma unroll
            for (int i = 0; i < 3; i++) {
                int u = tid + i * 512;
                int hi = (u < 768);
                int idx = hi ? u : u - 768;
                int r = idx >> 2, q = idx & 3;
                ws[i] = hi ? wp[r * 48 + qoff + q] : lp[r * 48 + qoff + q];
            }
        }

#pragma unroll
        for (int ks = 0; ks < 2; ks++) {
            const int k0 = ks * 16;
            uint32_t ah[2][4], al[2][4];
#pragma unroll
            for (int mi = 0; mi < 2; mi++) {
                int rb = wr * 32 + mi * 16 + g;
                ah[mi][0] = *(const uint32_t*)&sm[SM_AH + rb * ASTR + k0 + tg * 2];
                ah[mi][1] = *(const uint32_t*)&sm[SM_AH + (rb + 8) * ASTR + k0 + tg * 2];
                ah[mi][2] = *(const uint32_t*)&sm[SM_AH + rb * ASTR + k0 + 8 + tg * 2];
                ah[mi][3] = *(const uint32_t*)&sm[SM_AH + (rb + 8) * ASTR + k0 + 8 + tg * 2];
                al[mi][0] = *(const uint32_t*)&sm[SM_AL + rb * ASTR + k0 + tg * 2];
                al[mi][1] = *(const uint32_t*)&sm[SM_AL + (rb + 8) * ASTR + k0 + tg * 2];
                al[mi][2] = *(const uint32_t*)&sm[SM_AL + rb * ASTR + k0 + 8 + tg * 2];
                al[mi][3] = *(const uint32_t*)&sm[SM_AL + (rb + 8) * ASTR + k0 + 8 + tg * 2];
            }
#pragma unroll
            for (int ni = 0; ni < 6; ni++) {
                int n = wc * 48 + ni * 8 + g;
                uint32_t bh0 = *(const uint32_t*)&sm[SM_BH + n * ASTR + k0 + tg * 2];
                uint32_t bh1 = *(const uint32_t*)&sm[SM_BH + n * ASTR + k0 + 8 + tg * 2];
                uint32_t bl0 = *(const uint32_t*)&sm[SM_BL + n * ASTR + k0 + tg * 2];
                uint32_t bl1 = *(const uint32_t*)&sm[SM_BL + n * ASTR + k0 + 8 + tg * 2];
#pragma unroll
                for (int mi = 0; mi < 2; mi++) {
                    mma16816(acc[mi][ni], ah[mi], bh0, bh1);
                    mma16816(acc[mi][ni], al[mi], bh0, bh1);
                    mma16816(acc[mi][ni], ah[mi], bl0, bl1);
                }
            }
        }
        __syncthreads();
    }

#pragma unroll
    for (int mi = 0; mi < 2; mi++) {
        size_t m0 = row0 + wr * 32 + mi * 16 + g;
#pragma unroll
        for (int ni = 0; ni < 6; ni++) {
            int n = wc * 48 + ni * 8 + tg * 2;
            __nv_bfloat16 h0, l0, h1, l1, h2, l2, h3, l3;
            split1(acc[mi][ni][0], h0, l0); split1(acc[mi][ni][1], h1, l1);
            split1(acc[mi][ni][2], h2, l2); split1(acc[mi][ni][3], h3, l3);
            if (n < 128) {
                __nv_bfloat16* ph = (n < 64) ? g_qh : g_kh;
                __nv_bfloat16* pl = (n < 64) ? g_ql : g_kl;
                int col = n & 63;
                ((uint32_t*)ph)[(m0 * H_ + col) >> 1]       = pack2(h0, h1);
                ((uint32_t*)ph)[((m0 + 8) * H_ + col) >> 1] = pack2(h2, h3);
                ((uint32_t*)pl)[(m0 * H_ + col) >> 1]       = pack2(l0, l1);
                ((uint32_t*)pl)[((m0 + 8) * H_ + col) >> 1] = pack2(l2, l3);
            } else {
                int col = n - 128;
                size_t bb = m0 >> 8;
                int t = (int)(m0 & 255);
                size_t base = bb * (size_t)(H_ * T_);
                g_vh[base + col * T_ + t]           = h0;
                g_vh[base + (col + 1) * T_ + t]     = h1;
                g_vh[base + col * T_ + t + 8]       = h2;
                g_vh[base + (col + 1) * T_ + t + 8] = h3;
                g_vl[base + col * T_ + t]           = l0;
                g_vl[base + (col + 1) * T_ + t]     = l1;
                g_vl[base + col * T_ + t + 8]       = l2;
                g_vl[base + (col + 1) * T_ + t + 8] = l3;
            }
        }
    }
}

// ---------------------------------------------------------------------------
// Attention v3: flash-style. CTA = (batch, 128-query tile), 256 thr = 8 warps,
// each warp owns 16 full rows. Online softmax in registers, no S in smem.
// K/V fragments via ldmatrix.x4; P reused in-register as PV A-fragments.
// ---------------------------------------------------------------------------
#define KSTB 144                       // smem row stride (bytes) for K/V planes
#define PL   (64 * KSTB)               // 9216 B per plane
#define SMEM2 (4 * PL)                 // 36864 B

__global__ __launch_bounds__(256) void attn(float* __restrict__ out) {
    extern __shared__ char smc[];
    const uint32_t sb = smem_u32(smc);
    const uint32_t sKH = sb, sKL = sb + PL, sVH = sb + 2 * PL, sVL = sb + 3 * PL;

    const int b    = blockIdx.x;
    const int q0   = blockIdx.y * 128;
    const int tid  = threadIdx.x;
    const int lane = tid & 31;
    const int w    = tid >> 5;
    const int g    = lane >> 2;
    const int tg   = lane & 3;
    const int row0 = q0 + w * 16 + g;   // this thread's first row (also +8)

    // per-lane ldmatrix row/col offset within a 16x16 B sub-tile
    const uint32_t lmoff =
        (uint32_t)(((lane & 7) + ((lane >> 4) << 3)) * KSTB + ((lane >> 3) & 1) * 16);

    // ---- Q fragments (hi/lo) ----
    uint32_t qh[4][4], ql[4][4];
    {
        const size_t rb = (size_t)b * T_ + q0 + w * 16;
        const uint32_t* QH = (const uint32_t*)g_qh;
        const uint32_t* QL = (const uint32_t*)g_ql;
#pragma unroll
        for (int c = 0; c < 4; c++) {
            int d = c * 16 + tg * 2;
            qh[c][0] = QH[((rb + g) * H_ + d) >> 1];
            qh[c][1] = QH[((rb + g + 8) * H_ + d) >> 1];
            qh[c][2] = QH[((rb + g) * H_ + d + 8) >> 1];
            qh[c][3] = QH[((rb + g + 8) * H_ + d + 8) >> 1];
            ql[c][0] = QL[((rb + g) * H_ + d) >> 1];
            ql[c][1] = QL[((rb + g + 8) * H_ + d) >> 1];
            ql[c][2] = QL[((rb + g) * H_ + d + 8) >> 1];
            ql[c][3] = QL[((rb + g + 8) * H_ + d + 8) >> 1];
        }
    }

    float oacc[8][4];
#pragma unroll
    for (int f = 0; f < 8; f++)
#pragma unroll
        for (int r = 0; r < 4; r++) oacc[f][r] = 0.f;
    float m0 = -1e30f, m1 = -1e30f;     // running max, rows g / g+8
    float l0 = 0.f, l1 = 0.f;           // running (per-thread partial) sums

    const int ktmax = (q0 + 127) >> 6;  // inclusive
    for (int kt = 0; kt <= ktmax; kt++) {
        __syncthreads();
        {   // load K & V tiles (hi/lo planes)
            const uint4* KH = (const uint4*)g_kh;
            const uint4* KL = (const uint4*)g_kl;
            const uint4* VH = (const uint4*)g_vh;
            const uint4* VL = (const uint4*)g_vl;
#pragma unroll
            for (int i = 0; i < 2; i++) {
                int v = tid + i * 256;
                int r = v >> 3, c8 = v & 7;
                size_t ksrc = ((size_t)b * T_ + kt * 64 + r) * 8 + c8;
                size_t vsrc = (size_t)b * 2048 + (size_t)r * 32 + kt * 8 + c8;
                *(uint4*)(smc + (0 * PL) + r * KSTB + c8 * 16) = KH[ksrc];
                *(uint4*)(smc + (1 * PL) + r * KSTB + c8 * 16) = KL[ksrc];
                *(uint4*)(smc + (2 * PL) + r * KSTB + c8 * 16) = VH[vsrc];
                *(uint4*)(smc + (3 * PL) + r * KSTB + c8 * 16) = VL[vsrc];
            }
        }
        __syncthreads();

        if (kt * 64 > q0 + w * 16 + 15) continue;   // warp tile fully masked

        // ---- QK^T ----
        float sacc[8][4];
#pragma unroll
        for (int f = 0; f < 8; f++)
#pragma unroll
            for (int r = 0; r < 4; r++) sacc[f][r] = 0.f;

#pragma unroll
        for (int c = 0; c < 4; c++) {
            const uint32_t k2 = (uint32_t)(c * 32);   // k0*2 bytes
#pragma unroll
            for (int np = 0; np < 4; np++) {
                uint32_t bh0, bh1, bh2, bh3, bl0, bl1, bl2, bl3;
                uint32_t a0 = (uint32_t)(np * 16 * KSTB) + k2 + lmoff;
                ldm4(bh0, bh1, bh2, bh3, sKH + a0);
                ldm4(bl0, bl1, bl2, bl3, sKL + a0);
                mma16816(sacc[2 * np],     qh[c], bh0, bh1);
                mma16816(sacc[2 * np],     ql[c], bh0, bh1);
                mma16816(sacc[2 * np],     qh[c], bl0, bl1);
                mma16816(sacc[2 * np + 1], qh[c], bh2, bh3);
                mma16816(sacc[2 * np + 1], ql[c], bh2, bh3);
                mma16816(sacc[2 * np + 1], qh[c], bl2, bl3);
            }
        }

        // ---- scale + causal mask ----
        const bool diag = (kt * 64 + 63 > q0 + w * 16);
#pragma unroll
        for (int f = 0; f < 8; f++) {
            int colb = kt * 64 + f * 8 + tg * 2;
            if (diag) {
                sacc[f][0] = (colb     <= row0) ? sacc[f][0] * 0.125f : -1e30f;
                sacc[f][1] = (colb + 1 <= row0) ? sacc[f][1] * 0.125f : -1e30f;
                sacc[f][2] = (colb     <= row0 + 8) ? sacc[f][2] * 0.125f : -1e30f;
                sacc[f][3] = (colb + 1 <= row0 + 8) ? sacc[f][3] * 0.125f : -1e30f;
            } else {
                sacc[f][0] *= 0.125f; sacc[f][1] *= 0.125f;
                sacc[f][2] *= 0.125f; sacc[f][3] *= 0.125f;
            }
        }

        // ---- online softmax update ----
        float t0 = -1e30f, t1 = -1e30f;
#pragma unroll
        for (int f = 0; f < 8; f++) {
            t0 = fmaxf(t0, fmaxf(sacc[f][0], sacc[f][1]));
            t1 = fmaxf(t1, fmaxf(sacc[f][2], sacc[f][3]));
        }
        t0 = fmaxf(t0, __shfl_xor_sync(0xFFFFFFFFu, t0, 1));
        t0 = fmaxf(t0, __shfl_xor_sync(0xFFFFFFFFu, t0, 2));
        t1 = fmaxf(t1, __shfl_xor_sync(0xFFFFFFFFu, t1, 1));
        t1 = fmaxf(t1, __shfl_xor_sync(0xFFFFFFFFu, t1, 2));
        float mn0 = fmaxf(m0, t0), mn1 = fmaxf(m1, t1);
        float a0 = __expf(m0 - mn0), a1 = __expf(m1 - mn1);
        m0 = mn0; m1 = mn1;
        float s0 = 0.f, s1 = 0.f;
#pragma unroll
        for (int f = 0; f < 8; f++) {
            sacc[f][0] = __expf(sacc[f][0] - mn0);
            sacc[f][1] = __expf(sacc[f][1] - mn0);
            sacc[f][2] = __expf(sacc[f][2] - mn1);
            sacc[f][3] = __expf(sacc[f][3] - mn1);
            s0 += sacc[f][0] + sacc[f][1];
            s1 += sacc[f][2] + sacc[f][3];
        }
        l0 = l0 * a0 + s0;
        l1 = l1 * a1 + s1;
#pragma unroll
        for (int f = 0; f < 8; f++) {
            oacc[f][0] *= a0; oacc[f][1] *= a0;
            oacc[f][2] *= a1; oacc[f][3] *= a1;
        }

        // ---- PV: P fragments straight from sacc ----
#pragma unroll
        for (int c = 0; c < 4; c++) {
            uint32_t ph[4], pl[4];
            __nv_bfloat16 h0, lo0, h1, lo1;
            split1(sacc[2 * c][0], h0, lo0);  split1(sacc[2 * c][1], h1, lo1);
            ph[0] = pack2(h0, h1); pl[0] = pack2(lo0, lo1);
            split1(sacc[2 * c][2], h0, lo0);  split1(sacc[2 * c][3], h1, lo1);
            ph[1] = pack2(h0, h1); pl[1] = pack2(lo0, lo1);
            split1(sacc[2 * c + 1][0], h0, lo0); split1(sacc[2 * c + 1][1], h1, lo1);
            ph[2] = pack2(h0, h1); pl[2] = pack2(lo0, lo1);
            split1(sacc[2 * c + 1][2], h0, lo0); split1(sacc[2 * c + 1][3], h1, lo1);
            ph[3] = pack2(h0, h1); pl[3] = pack2(lo0, lo1);

            const uint32_t k2 = (uint32_t)(c * 32);
#pragma unroll
            for (int np = 0; np < 4; np++) {
                uint32_t vh0, vh1, vh2, vh3, vl0, vl1, vl2, vl3;
                uint32_t a = (uint32_t)(np * 16 * KSTB) + k2 + lmoff;
                ldm4(vh0, vh1, vh2, vh3, sVH + a);
                ldm4(vl0, vl1, vl2, vl3, sVL + a);
                mma16816(oacc[2 * np],     ph, vh0, vh1);
                mma16816(oacc[2 * np],     pl, vh0, vh1);
                mma16816(oacc[2 * np],     ph, vl0, vl1);
                mma16816(oacc[2 * np + 1], ph, vh2, vh3);
                mma16816(oacc[2 * np + 1], pl, vh2, vh3);
                mma16816(oacc[2 * np + 1], ph, vl2, vl3);
            }
        }
    }

    // ---- finalize: reduce l across quad, normalize, store ----
    l0 += __shfl_xor_sync(0xFFFFFFFFu, l0, 1);
    l0 += __shfl_xor_sync(0xFFFFFFFFu, l0, 2);
    l1 += __shfl_xor_sync(0xFFFFFFFFu, l1, 1);
    l1 += __shfl_xor_sync(0xFFFFFFFFu, l1, 2);
    float i0 = 1.f / l0, i1 = 1.f / l1;
    {
        size_t r0 = (size_t)b * T_ + row0;
#pragma unroll
        for (int f = 0; f < 8; f++) {
            int col = f * 8 + tg * 2;
            *(float2*)&out[r0 * H_ + col] =
                make_float2(oacc[f][0] * i0, oacc[f][1] * i0);
            *(float2*)&out[(r0 + 8) * H_ + col] =
                make_float2(oacc[f][2] * i1, oacc[f][3] * i1);
        }
    }
}

// ---------------------------------------------------------------------------
extern "C" void kernel_launch(void* const* d_in, const int* in_sizes, int n_in,
                              void* d_out, int out_size) {
    const float* x  = (const float*)d_in[0];
    const float* Wq = (const float*)d_in[1];
    const float* Wk = (const float*)d_in[2];
    const float* Wv = (const float*)d_in[3];
    float* out = (float*)d_out;
    (void)in_sizes; (void)n_in; (void)out_size;

    cudaFuncSetAttribute(qkv_mma, cudaFuncAttributeMaxDynamicSharedMemorySize, SMEMQ);
    cudaFuncSetAttribute(attn, cudaFuncAttributeMaxDynamicSharedMemorySize, SMEM2);

    wprep<<<(NTOT * C_ + 255) / 256, 256>>>(Wq, Wk, Wv);
    qkv_mma<<<(B_ * T_) / 128, 512, SMEMQ>>>(x);
    attn<<<dim3(B_, T_ / 128), 256, SMEM2>>>(out);
}

// round 7
// speedup vs baseline: 2.1425x; 1.0492x over previous
#include <cuda_runtime.h>
#include <cuda_bf16.h>
#include <cstdint>

#define B_ 512
#define T_ 256
#define C_ 384
#define H_ 64
#define NTOT 192

// split-bf16 q/k planes, row-major [tok][dim]
__device__ __align__(16) __nv_bfloat16 g_qh[B_ * T_ * H_];
__device__ __align__(16) __nv_bfloat16 g_ql[B_ * T_ * H_];
__device__ __align__(16) __nv_bfloat16 g_kh[B_ * T_ * H_];
__device__ __align__(16) __nv_bfloat16 g_kl[B_ * T_ * H_];
// split-bf16 v planes, transposed per batch [b][dim][tok]
__device__ __align__(16) __nv_bfloat16 g_vh[B_ * T_ * H_];
__device__ __align__(16) __nv_bfloat16 g_vl[B_ * T_ * H_];
// pre-split weights, K-major [n(q|k|v)][384]
__device__ __align__(16) __nv_bfloat16 gWhi[NTOT * C_];
__device__ __align__(16) __nv_bfloat16 gWlo[NTOT * C_];

__device__ __forceinline__ void split1(float v, __nv_bfloat16& h, __nv_bfloat16& l) {
    h = __float2bfloat16(v);
    l = __float2bfloat16(v - __bfloat162float(h));
}
__device__ __forceinline__ uint32_t pack2(__nv_bfloat16 a, __nv_bfloat16 b) {
    __nv_bfloat162 t = __halves2bfloat162(a, b);
    uint32_t u; memcpy(&u, &t, 4); return u;
}
__device__ __forceinline__ void mma16816(float* d, const uint32_t* a,
                                         uint32_t b0, uint32_t b1) {
    asm volatile(
        "mma.sync.aligned.m16n8k16.row.col.f32.bf16.bf16.f32 "
        "{%0,%1,%2,%3},{%4,%5,%6,%7},{%8,%9},{%0,%1,%2,%3};"
        : "+f"(d[0]), "+f"(d[1]), "+f"(d[2]), "+f"(d[3])
        : "r"(a[0]), "r"(a[1]), "r"(a[2]), "r"(a[3]), "r"(b0), "r"(b1));
}
__device__ __forceinline__ void ldm4(uint32_t& r0, uint32_t& r1, uint32_t& r2,
                                     uint32_t& r3, uint32_t addr) {
    asm volatile("ldmatrix.sync.aligned.m8n8.x4.shared.b16 {%0,%1,%2,%3},[%4];"
                 : "=r"(r0), "=r"(r1), "=r"(r2), "=r"(r3) : "r"(addr));
}
__device__ __forceinline__ uint32_t smem_u32(const void* p) {
    uint32_t a;
    asm("{ .reg .u64 t; cvta.to.shared.u64 t, %1; cvt.u32.u64 %0, t; }"
        : "=r"(a) : "l"(p));
    return a;
}
__device__ __forceinline__ void cpa16(uint32_t dst, const void* src) {
    asm volatile("cp.async.cg.shared.global [%0], [%1], 16;"
                 :: "r"(dst), "l"(src) : "memory");
}
#define CP_COMMIT() asm volatile("cp.async.commit_group;" ::: "memory")
#define CP_WAIT(n)  asm volatile("cp.async.wait_group %0;" :: "n"(n) : "memory")

// ------------------------------------------------------- weight prep (tiny)
__global__ void wprep(const float* __restrict__ Wq, const float* __restrict__ Wk,
                      const float* __restrict__ Wv) {
    int i = blockIdx.x * 256 + threadIdx.x;
    if (i >= NTOT * C_) return;
    int n = i / C_, ck = i % C_;
    const float* W = (n < 64) ? Wq : ((n < 128) ? Wk : Wv);
    float w = W[ck * H_ + (n & 63)];
    __nv_bfloat16 h, l; split1(w, h, l);
    gWhi[i] = h; gWlo[i] = l;
}

// ---------------------------------------------------------------------------
// QKV projection: split-bf16 3-term mma.sync, ldmatrix fragment loads.
// ---------------------------------------------------------------------------
#define BKQ 32
#define ASTR 40
#define SM_AH 0
#define SM_AL (128 * ASTR)
#define SM_BH (2 * 128 * ASTR)
#define SM_BL (2 * 128 * ASTR + 192 * ASTR)
// byte offsets
#define AHB 0
#define ALB (SM_AL * 2)
#define BHB (SM_BH * 2)
#define BLB (SM_BL * 2)
#define SMEMQ ((2 * 128 * ASTR + 2 * 192 * ASTR) * 2)

__global__ __launch_bounds__(512, 1) void qkv_mma(const float* __restrict__ x) {
    extern __shared__ __nv_bfloat16 sm[];
    const uint32_t sbq = smem_u32(sm);
    const int tid  = threadIdx.x;
    const int w    = tid >> 5;
    const int lane = tid & 31;
    const int g    = lane >> 2;
    const int tg   = lane & 3;
    const int wr   = w >> 2;
    const int wc   = w & 3;
    const size_t row0 = (size_t)blockIdx.x * 128;

    // ldmatrix per-lane offsets (stride 80 B rows)
    const uint32_t lmA = (uint32_t)((lane & 15) * 80 + (lane >> 4) * 16);
    const uint32_t lmB = (uint32_t)(((lane & 7) + ((lane >> 4) << 3)) * 80 +
                                    ((lane >> 3) & 1) * 16);

    float acc[2][6][4];
#pragma unroll
    for (int mi = 0; mi < 2; mi++)
#pragma unroll
        for (int ni = 0; ni < 6; ni++)
#pragma unroll
            for (int r = 0; r < 4; r++) acc[mi][ni][r] = 0.f;

    float4 xs[2];
    uint4  ws[3];
    {
        const float* xp = x + row0 * C_;
#pragma unroll
        for (int i = 0; i < 2; i++) {
            int v = tid + i * 512;
            int r = v >> 3, cf = v & 7;
            xs[i] = *(const float4*)(xp + (size_t)r * C_ + cf * 4);
        }
        const uint4* wp = (const uint4*)gWhi;
        const uint4* lp = (const uint4*)gWlo;
#pragma unroll
        for (int i = 0; i < 3; i++) {
            int u = tid + i * 512;
            int hi = (u < 768);
            int idx = hi ? u : u - 768;
            int r = idx >> 2, q = idx & 3;
            ws[i] = hi ? wp[r * 48 + q] : lp[r * 48 + q];
        }
    }

    const int NCH = C_ / BKQ;
    for (int c = 0; c < NCH; c++) {
#pragma unroll
        for (int i = 0; i < 2; i++) {
            int v = tid + i * 512;
            int r = v >> 3, cf = v & 7;
            __nv_bfloat16 h0, l0, h1, l1, h2, l2, h3, l3;
            split1(xs[i].x, h0, l0); split1(xs[i].y, h1, l1);
            split1(xs[i].z, h2, l2); split1(xs[i].w, h3, l3);
            uint32_t* ph = (uint32_t*)&sm[SM_AH + r * ASTR + cf * 4];
            uint32_t* pl = (uint32_t*)&sm[SM_AL + r * ASTR + cf * 4];
            ph[0] = pack2(h0, h1); ph[1] = pack2(h2, h3);
            pl[0] = pack2(l0, l1); pl[1] = pack2(l2, l3);
        }
#pragma unroll
        for (int i = 0; i < 3; i++) {
            int u = tid + i * 512;
            int hi = (u < 768);
            int idx = hi ? u : u - 768;
            int r = idx >> 2, q = idx & 3;
            uint32_t* p = (uint32_t*)&sm[(hi ? SM_BH : SM_BL) + r * ASTR + q * 8];
            p[0] = ws[i].x; p[1] = ws[i].y; p[2] = ws[i].z; p[3] = ws[i].w;
        }
        __syncthreads();

        if (c + 1 < NCH) {
            const int c0 = (c + 1) * BKQ;
            const float* xp = x + row0 * C_ + c0;
#pragma unroll
            for (int i = 0; i < 2; i++) {
                int v = tid + i * 512;
                int r = v >> 3, cf = v & 7;
                xs[i] = *(const float4*)(xp + (size_t)r * C_ + cf * 4);
            }
            const uint4* wp = (const uint4*)gWhi;
            const uint4* lp = (const uint4*)gWlo;
            const int qoff = c0 / 8;
#pragma unroll
            for (int i = 0; i < 3; i++) {
                int u = tid + i * 512;
                int hi = (u < 768);
                int idx = hi ? u : u - 768;
                int r = idx >> 2, q = idx & 3;
                ws[i] = hi ? wp[r * 48 + qoff + q] : lp[r * 48 + qoff + q];
            }
        }

        // ---- compute: ldmatrix fragments + 3-term MMA ----
#pragma unroll
        for (int ks = 0; ks < 2; ks++) {
            const uint32_t k2 = (uint32_t)(ks * 32);   // byte offset of k0
            uint32_t ah[2][4], al[2][4];
#pragma unroll
            for (int mi = 0; mi < 2; mi++) {
                uint32_t ao = (uint32_t)((wr * 32 + mi * 16) * 80) + k2 + lmA;
                ldm4(ah[mi][0], ah[mi][1], ah[mi][2], ah[mi][3], sbq + AHB + ao);
                ldm4(al[mi][0], al[mi][1], al[mi][2], al[mi][3], sbq + ALB + ao);
            }
#pragma unroll
            for (int npi = 0; npi < 3; npi++) {
                uint32_t bh[4], bl[4];
                uint32_t bo = (uint32_t)((wc * 48 + npi * 16) * 80) + k2 + lmB;
                ldm4(bh[0], bh[1], bh[2], bh[3], sbq + BHB + bo);
                ldm4(bl[0], bl[1], bl[2], bl[3], sbq + BLB + bo);
#pragma unroll
                for (int half = 0; half < 2; half++) {
                    int ni = npi * 2 + half;
                    uint32_t b0 = bh[2 * half], b1 = bh[2 * half + 1];
                    uint32_t c0 = bl[2 * half], c1 = bl[2 * half + 1];
#pragma unroll
                    for (int mi = 0; mi < 2; mi++) {
                        mma16816(acc[mi][ni], ah[mi], b0, b1);
                        mma16816(acc[mi][ni], al[mi], b0, b1);
                        mma16816(acc[mi][ni], ah[mi], c0, c1);
                    }
                }
            }
        }
        __syncthreads();
    }

#pragma unroll
    for (int mi = 0; mi < 2; mi++) {
        size_t m0 = row0 + wr * 32 + mi * 16 + g;
#pragma unroll
        for (int ni = 0; ni < 6; ni++) {
            int n = wc * 48 + ni * 8 + tg * 2;
            __nv_bfloat16 h0, l0, h1, l1, h2, l2, h3, l3;
            split1(acc[mi][ni][0], h0, l0); split1(acc[mi][ni][1], h1, l1);
            split1(acc[mi][ni][2], h2, l2); split1(acc[mi][ni][3], h3, l3);
            if (n < 128) {
                __nv_bfloat16* ph = (n < 64) ? g_qh : g_kh;
                __nv_bfloat16* pl = (n < 64) ? g_ql : g_kl;
                int col = n & 63;
                ((uint32_t*)ph)[(m0 * H_ + col) >> 1]       = pack2(h0, h1);
                ((uint32_t*)ph)[((m0 + 8) * H_ + col) >> 1] = pack2(h2, h3);
                ((uint32_t*)pl)[(m0 * H_ + col) >> 1]       = pack2(l0, l1);
                ((uint32_t*)pl)[((m0 + 8) * H_ + col) >> 1] = pack2(l2, l3);
            } else {
                int col = n - 128;
                size_t bb = m0 >> 8;
                int t = (int)(m0 & 255);
                size_t base = bb * (size_t)(H_ * T_);
                g_vh[base + col * T_ + t]           = h0;
                g_vh[base + (col + 1) * T_ + t]     = h1;
                g_vh[base + col * T_ + t + 8]       = h2;
                g_vh[base + (col + 1) * T_ + t + 8] = h3;
                g_vl[base + col * T_ + t]           = l0;
                g_vl[base + (col + 1) * T_ + t]     = l1;
                g_vl[base + col * T_ + t + 8]       = l2;
                g_vl[base + (col + 1) * T_ + t + 8] = l3;
            }
        }
    }
}

// ---------------------------------------------------------------------------
// Attention v4: flash-style + cp.async double-buffered K/V tiles.
// CTA = (batch, 128-query tile), 256 thr = 8 warps, 16 rows/warp.
// ---------------------------------------------------------------------------
#define KSTB 144
#define PL   (64 * KSTB)               // 9216 B per plane
#define BUFA (4 * PL)                  // 36864 B per pipeline buffer
#define SMEM2 (2 * BUFA)               // 73728 B

__global__ __launch_bounds__(256) void attn(float* __restrict__ out) {
    extern __shared__ char smc[];
    const uint32_t sb = smem_u32(smc);

    const int b    = blockIdx.x;
    const int q0   = blockIdx.y * 128;
    const int tid  = threadIdx.x;
    const int lane = tid & 31;
    const int w    = tid >> 5;
    const int g    = lane >> 2;
    const int tg   = lane & 3;
    const int row0 = q0 + w * 16 + g;

    const uint32_t lmoff =
        (uint32_t)(((lane & 7) + ((lane >> 4) << 3)) * KSTB + ((lane >> 3) & 1) * 16);

    // per-thread load slots (same for every tile)
    const int lr0 = tid >> 3, lc0 = tid & 7;            // slot 0
    const int lr1 = (tid + 256) >> 3, lc1 = tid & 7;    // slot 1

    auto issue = [&](int kt, int buf) {
        const uint4* KH = (const uint4*)g_kh;
        const uint4* KL = (const uint4*)g_kl;
        const uint4* VH = (const uint4*)g_vh;
        const uint4* VL = (const uint4*)g_vl;
        uint32_t base = sb + buf * BUFA;
#pragma unroll
        for (int i = 0; i < 2; i++) {
            int r  = i ? lr1 : lr0;
            int c8 = i ? lc1 : lc0;
            size_t ksrc = ((size_t)b * T_ + kt * 64 + r) * 8 + c8;
            size_t vsrc = (size_t)b * 2048 + (size_t)r * 32 + kt * 8 + c8;
            uint32_t d = (uint32_t)(r * KSTB + c8 * 16);
            cpa16(base + 0 * PL + d, KH + ksrc);
            cpa16(base + 1 * PL + d, KL + ksrc);
            cpa16(base + 2 * PL + d, VH + vsrc);
            cpa16(base + 3 * PL + d, VL + vsrc);
        }
    };

    // ---- Q fragments (hi/lo) ----
    uint32_t qh[4][4], ql[4][4];
    {
        const size_t rb = (size_t)b * T_ + q0 + w * 16;
        const uint32_t* QH = (const uint32_t*)g_qh;
        const uint32_t* QL = (const uint32_t*)g_ql;
#pragma unroll
        for (int c = 0; c < 4; c++) {
            int d = c * 16 + tg * 2;
            qh[c][0] = QH[((rb + g) * H_ + d) >> 1];
            qh[c][1] = QH[((rb + g + 8) * H_ + d) >> 1];
            qh[c][2] = QH[((rb + g) * H_ + d + 8) >> 1];
            qh[c][3] = QH[((rb + g + 8) * H_ + d + 8) >> 1];
            ql[c][0] = QL[((rb + g) * H_ + d) >> 1];
            ql[c][1] = QL[((rb + g + 8) * H_ + d) >> 1];
            ql[c][2] = QL[((rb + g) * H_ + d + 8) >> 1];
            ql[c][3] = QL[((rb + g + 8) * H_ + d + 8) >> 1];
        }
    }

    float oacc[8][4];
#pragma unroll
    for (int f = 0; f < 8; f++)
#pragma unroll
        for (int r = 0; r < 4; r++) oacc[f][r] = 0.f;
    float m0 = -1e30f, m1 = -1e30f;
    float l0 = 0.f, l1 = 0.f;

    const int ktmax = (q0 + 127) >> 6;

    issue(0, 0);
    CP_COMMIT();

    for (int kt = 0; kt <= ktmax; kt++) {
        if (kt < ktmax) {
            issue(kt + 1, (kt + 1) & 1);
            CP_COMMIT();
            CP_WAIT(1);
        } else {
            CP_WAIT(0);
        }
        __syncthreads();

        if (kt * 64 <= q0 + w * 16 + 15) {
            const uint32_t bb = sb + (kt & 1) * BUFA;
            const uint32_t sKH = bb, sKL = bb + PL, sVH = bb + 2 * PL,
                           sVL = bb + 3 * PL;

            // ---- QK^T ----
            float sacc[8][4];
#pragma unroll
            for (int f = 0; f < 8; f++)
#pragma unroll
                for (int r = 0; r < 4; r++) sacc[f][r] = 0.f;

#pragma unroll
            for (int c = 0; c < 4; c++) {
                const uint32_t k2 = (uint32_t)(c * 32);
#pragma unroll
                for (int np = 0; np < 4; np++) {
                    uint32_t bh0, bh1, bh2, bh3, bl0, bl1, bl2, bl3;
                    uint32_t a0 = (uint32_t)(np * 16 * KSTB) + k2 + lmoff;
                    ldm4(bh0, bh1, bh2, bh3, sKH + a0);
                    ldm4(bl0, bl1, bl2, bl3, sKL + a0);
                    mma16816(sacc[2 * np],     qh[c], bh0, bh1);
                    mma16816(sacc[2 * np],     ql[c], bh0, bh1);
                    mma16816(sacc[2 * np],     qh[c], bl0, bl1);
                    mma16816(sacc[2 * np + 1], qh[c], bh2, bh3);
                    mma16816(sacc[2 * np + 1], ql[c], bh2, bh3);
                    mma16816(sacc[2 * np + 1], qh[c], bl2, bl3);
                }
            }

            // ---- scale + causal mask ----
            const bool diag = (kt * 64 + 63 > q0 + w * 16);
#pragma unroll
            for (int f = 0; f < 8; f++) {
                int colb = kt * 64 + f * 8 + tg * 2;
                if (diag) {
                    sacc[f][0] = (colb     <= row0) ? sacc[f][0] * 0.125f : -1e30f;
                    sacc[f][1] = (colb + 1 <= row0) ? sacc[f][1] * 0.125f : -1e30f;
                    sacc[f][2] = (colb     <= row0 + 8) ? sacc[f][2] * 0.125f : -1e30f;
                    sacc[f][3] = (colb + 1 <= row0 + 8) ? sacc[f][3] * 0.125f : -1e30f;
                } else {
                    sacc[f][0] *= 0.125f; sacc[f][1] *= 0.125f;
                    sacc[f][2] *= 0.125f; sacc[f][3] *= 0.125f;
                }
            }

            // ---- online softmax update ----
            float t0 = -1e30f, t1 = -1e30f;
#pragma unroll
            for (int f = 0; f < 8; f++) {
                t0 = fmaxf(t0, fmaxf(sacc[f][0], sacc[f][1]));
                t1 = fmaxf(t1, fmaxf(sacc[f][2], sacc[f][3]));
            }
            t0 = fmaxf(t0, __shfl_xor_sync(0xFFFFFFFFu, t0, 1));
            t0 = fmaxf(t0, __shfl_xor_sync(0xFFFFFFFFu, t0, 2));
            t1 = fmaxf(t1, __shfl_xor_sync(0xFFFFFFFFu, t1, 1));
            t1 = fmaxf(t1, __shfl_xor_sync(0xFFFFFFFFu, t1, 2));
            float mn0 = fmaxf(m0, t0), mn1 = fmaxf(m1, t1);
            float a0 = __expf(m0 - mn0), a1 = __expf(m1 - mn1);
            m0 = mn0; m1 = mn1;
            float s0 = 0.f, s1 = 0.f;
#pragma unroll
            for (int f = 0; f < 8; f++) {
                sacc[f][0] = __expf(sacc[f][0] - mn0);
                sacc[f][1] = __expf(sacc[f][1] - mn0);
                sacc[f][2] = __expf(sacc[f][2] - mn1);
                sacc[f][3] = __expf(sacc[f][3] - mn1);
                s0 += sacc[f][0] + sacc[f][1];
                s1 += sacc[f][2] + sacc[f][3];
            }
            l0 = l0 * a0 + s0;
            l1 = l1 * a1 + s1;
#pragma unroll
            for (int f = 0; f < 8; f++) {
                oacc[f][0] *= a0; oacc[f][1] *= a0;
                oacc[f][2] *= a1; oacc[f][3] *= a1;
            }

            // ---- PV ----
#pragma unroll
            for (int c = 0; c < 4; c++) {
                uint32_t ph[4], pl[4];
                __nv_bfloat16 h0, lo0, h1, lo1;
                split1(sacc[2 * c][0], h0, lo0);  split1(sacc[2 * c][1], h1, lo1);
                ph[0] = pack2(h0, h1); pl[0] = pack2(lo0, lo1);
                split1(sacc[2 * c][2], h0, lo0);  split1(sacc[2 * c][3], h1, lo1);
                ph[1] = pack2(h0, h1); pl[1] = pack2(lo0, lo1);
                split1(sacc[2 * c + 1][0], h0, lo0); split1(sacc[2 * c + 1][1], h1, lo1);
                ph[2] = pack2(h0, h1); pl[2] = pack2(lo0, lo1);
                split1(sacc[2 * c + 1][2], h0, lo0); split1(sacc[2 * c + 1][3], h1, lo1);
                ph[3] = pack2(h0, h1); pl[3] = pack2(lo0, lo1);

                const uint32_t k2 = (uint32_t)(c * 32);
#pragma unroll
                for (int np = 0; np < 4; np++) {
                    uint32_t vh0, vh1, vh2, vh3, vl0, vl1, vl2, vl3;
                    uint32_t a = (uint32_t)(np * 16 * KSTB) + k2 + lmoff;
                    ldm4(vh0, vh1, vh2, vh3, sVH + a);
                    ldm4(vl0, vl1, vl2, vl3, sVL + a);
                    mma16816(oacc[2 * np],     ph, vh0, vh1);
                    mma16816(oacc[2 * np],     pl, vh0, vh1);
                    mma16816(oacc[2 * np],     ph, vl0, vl1);
                    mma16816(oacc[2 * np + 1], ph, vh2, vh3);
                    mma16816(oacc[2 * np + 1], pl, vh2, vh3);
                    mma16816(oacc[2 * np + 1], ph, vl2, vl3);
                }
            }
        }
        __syncthreads();
    }

    // ---- finalize ----
    l0 += __shfl_xor_sync(0xFFFFFFFFu, l0, 1);
    l0 += __shfl_xor_sync(0xFFFFFFFFu, l0, 2);
    l1 += __shfl_xor_sync(0xFFFFFFFFu, l1, 1);
    l1 += __shfl_xor_sync(0xFFFFFFFFu, l1, 2);
    float i0 = 1.f / l0, i1 = 1.f / l1;
    {
        size_t r0 = (size_t)b * T_ + row0;
#pragma unroll
        for (int f = 0; f < 8; f++) {
            int col = f * 8 + tg * 2;
            *(float2*)&out[r0 * H_ + col] =
                make_float2(oacc[f][0] * i0, oacc[f][1] * i0);
            *(float2*)&out[(r0 + 8) * H_ + col] =
                make_float2(oacc[f][2] * i1, oacc[f][3] * i1);
        }
    }
}

// ---------------------------------------------------------------------------
extern "C" void kernel_launch(void* const* d_in, const int* in_sizes, int n_in,
                              void* d_out, int out_size) {
    const float* x  = (const float*)d_in[0];
    const float* Wq = (const float*)d_in[1];
    const float* Wk = (const float*)d_in[2];
    const float* Wv = (const float*)d_in[3];
    float* out = (float*)d_out;
    (void)in_sizes; (void)n_in; (void)out_size;

    cudaFuncSetAttribute(qkv_mma, cudaFuncAttributeMaxDynamicSharedMemorySize, SMEMQ);
    cudaFuncSetAttribute(attn, cudaFuncAttributeMaxDynamicSharedMemorySize, SMEM2);

    wprep<<<(NTOT * C_ + 255) / 256, 256>>>(Wq, Wk, Wv);
    qkv_mma<<<(B_ * T_) / 128, 512, SMEMQ>>>(x);
    attn<<<dim3(B_, T_ / 128), 256, SMEM2>>>(out);
}

// round 8
// speedup vs baseline: 2.4363x; 1.1371x over previous
#include <cuda_runtime.h>
#include <cuda_bf16.h>
#include <cuda_fp16.h>
#include <cstdint>

#define B_ 512
#define T_ 256
#define C_ 384
#define H_ 64
#define NTOT 192

// split-bf16 q/k planes, row-major [tok][dim]
__device__ __align__(16) __nv_bfloat16 g_qh[B_ * T_ * H_];
__device__ __align__(16) __nv_bfloat16 g_ql[B_ * T_ * H_];
__device__ __align__(16) __nv_bfloat16 g_kh[B_ * T_ * H_];
__device__ __align__(16) __nv_bfloat16 g_kl[B_ * T_ * H_];
// split-fp16 v planes, transposed per batch [b][dim][tok]
__device__ __align__(16) __half g_vh[B_ * T_ * H_];
__device__ __align__(16) __half g_vl[B_ * T_ * H_];
// pre-split weights, K-major [n(q|k|v)][384]
__device__ __align__(16) __nv_bfloat16 gWhi[NTOT * C_];
__device__ __align__(16) __nv_bfloat16 gWlo[NTOT * C_];

__device__ __forceinline__ void split1(float v, __nv_bfloat16& h, __nv_bfloat16& l) {
    h = __float2bfloat16(v);
    l = __float2bfloat16(v - __bfloat162float(h));
}
__device__ __forceinline__ void split1h(float v, __half& h, __half& l) {
    h = __float2half_rn(v);
    l = __float2half_rn(v - __half2float(h));
}
__device__ __forceinline__ uint32_t pack2(__nv_bfloat16 a, __nv_bfloat16 b) {
    __nv_bfloat162 t = __halves2bfloat162(a, b);
    uint32_t u; memcpy(&u, &t, 4); return u;
}
__device__ __forceinline__ uint32_t pack2h(__half a, __half b) {
    __half2 t = __halves2half2(a, b);
    uint32_t u; memcpy(&u, &t, 4); return u;
}
__device__ __forceinline__ void mma16816(float* d, const uint32_t* a,
                                         uint32_t b0, uint32_t b1) {
    asm volatile(
        "mma.sync.aligned.m16n8k16.row.col.f32.bf16.bf16.f32 "
        "{%0,%1,%2,%3},{%4,%5,%6,%7},{%8,%9},{%0,%1,%2,%3};"
        : "+f"(d[0]), "+f"(d[1]), "+f"(d[2]), "+f"(d[3])
        : "r"(a[0]), "r"(a[1]), "r"(a[2]), "r"(a[3]), "r"(b0), "r"(b1));
}
__device__ __forceinline__ void mma16816h(float* d, const uint32_t* a,
                                          uint32_t b0, uint32_t b1) {
    asm volatile(
        "mma.sync.aligned.m16n8k16.row.col.f32.f16.f16.f32 "
        "{%0,%1,%2,%3},{%4,%5,%6,%7},{%8,%9},{%0,%1,%2,%3};"
        : "+f"(d[0]), "+f"(d[1]), "+f"(d[2]), "+f"(d[3])
        : "r"(a[0]), "r"(a[1]), "r"(a[2]), "r"(a[3]), "r"(b0), "r"(b1));
}
__device__ __forceinline__ void ldm4(uint32_t& r0, uint32_t& r1, uint32_t& r2,
                                     uint32_t& r3, uint32_t addr) {
    asm volatile("ldmatrix.sync.aligned.m8n8.x4.shared.b16 {%0,%1,%2,%3},[%4];"
                 : "=r"(r0), "=r"(r1), "=r"(r2), "=r"(r3) : "r"(addr));
}
__device__ __forceinline__ uint32_t smem_u32(const void* p) {
    uint32_t a;
    asm("{ .reg .u64 t; cvta.to.shared.u64 t, %1; cvt.u32.u64 %0, t; }"
        : "=r"(a) : "l"(p));
    return a;
}
__device__ __forceinline__ void cpa16(uint32_t dst, const void* src) {
    asm volatile("cp.async.cg.shared.global [%0], [%1], 16;"
                 :: "r"(dst), "l"(src) : "memory");
}
#define CP_COMMIT() asm volatile("cp.async.commit_group;" ::: "memory")
#define CP_WAIT(n)  asm volatile("cp.async.wait_group %0;" :: "n"(n) : "memory")

// ------------------------------------------------------- weight prep (tiny)
__global__ void wprep(const float* __restrict__ Wq, const float* __restrict__ Wk,
                      const float* __restrict__ Wv) {
    int i = blockIdx.x * 256 + threadIdx.x;
    if (i >= NTOT * C_) return;
    int n = i / C_, ck = i % C_;
    const float* W = (n < 64) ? Wq : ((n < 128) ? Wk : Wv);
    float w = W[ck * H_ + (n & 63)];
    __nv_bfloat16 h, l; split1(w, h, l);
    gWhi[i] = h; gWlo[i] = l;
}

// ---------------------------------------------------------------------------
// QKV projection: split-bf16 3-term mma.sync, ldmatrix, double-buffered smem.
// ---------------------------------------------------------------------------
#define BKQ 32
#define ASTR 40
#define SM_AH 0
#define SM_AL (128 * ASTR)
#define SM_BH (2 * 128 * ASTR)
#define SM_BL (2 * 128 * ASTR + 192 * ASTR)
#define AHB 0
#define ALB (SM_AL * 2)
#define BHB (SM_BH * 2)
#define BLB (SM_BL * 2)
#define BUFEL (2 * 128 * ASTR + 2 * 192 * ASTR)   // 25600 elements
#define BUFBY (BUFEL * 2)                          // 51200 bytes
#define SMEMQ (2 * BUFBY)                          // 102400 bytes

__global__ __launch_bounds__(512, 1) void qkv_mma(const float* __restrict__ x) {
    extern __shared__ __nv_bfloat16 sm[];
    const uint32_t sbq = smem_u32(sm);
    const int tid  = threadIdx.x;
    const int w    = tid >> 5;
    const int lane = tid & 31;
    const int g    = lane >> 2;
    const int tg   = lane & 3;
    const int wr   = w >> 2;
    const int wc   = w & 3;
    const size_t row0 = (size_t)blockIdx.x * 128;

    const uint32_t lmA = (uint32_t)((lane & 15) * 80 + (lane >> 4) * 16);
    const uint32_t lmB = (uint32_t)(((lane & 7) + ((lane >> 4) << 3)) * 80 +
                                    ((lane >> 3) & 1) * 16);

    float acc[2][6][4];
#pragma unroll
    for (int mi = 0; mi < 2; mi++)
#pragma unroll
        for (int ni = 0; ni < 6; ni++)
#pragma unroll
            for (int r = 0; r < 4; r++) acc[mi][ni][r] = 0.f;

    float4 xs[2];
    uint4  ws[3];
    {
        const float* xp = x + row0 * C_;
#pragma unroll
        for (int i = 0; i < 2; i++) {
            int v = tid + i * 512;
            int r = v >> 3, cf = v & 7;
            xs[i] = *(const float4*)(xp + (size_t)r * C_ + cf * 4);
        }
        const uint4* wp = (const uint4*)gWhi;
        const uint4* lp = (const uint4*)gWlo;
#pragma unroll
        for (int i = 0; i < 3; i++) {
            int u = tid + i * 512;
            int hi = (u < 768);
            int idx = hi ? u : u - 768;
            int r = idx >> 2, q = idx & 3;
            ws[i] = hi ? wp[r * 48 + q] : lp[r * 48 + q];
        }
    }

    const int NCH = C_ / BKQ;
    for (int c = 0; c < NCH; c++) {
        __nv_bfloat16* smb = sm + (c & 1) * BUFEL;
        // ---- store staged chunk c (split x; copy w) ----
#pragma unroll
        for (int i = 0; i < 2; i++) {
            int v = tid + i * 512;
            int r = v >> 3, cf = v & 7;
            __nv_bfloat16 h0, l0, h1, l1, h2, l2, h3, l3;
            split1(xs[i].x, h0, l0); split1(xs[i].y, h1, l1);
            split1(xs[i].z, h2, l2); split1(xs[i].w, h3, l3);
            uint32_t* ph = (uint32_t*)&smb[SM_AH + r * ASTR + cf * 4];
            uint32_t* pl = (uint32_t*)&smb[SM_AL + r * ASTR + cf * 4];
            ph[0] = pack2(h0, h1); ph[1] = pack2(h2, h3);
            pl[0] = pack2(l0, l1); pl[1] = pack2(l2, l3);
        }
#pragma unroll
        for (int i = 0; i < 3; i++) {
            int u = tid + i * 512;
            int hi = (u < 768);
            int idx = hi ? u : u - 768;
            int r = idx >> 2, q = idx & 3;
            uint32_t* p = (uint32_t*)&smb[(hi ? SM_BH : SM_BL) + r * ASTR + q * 8];
            p[0] = ws[i].x; p[1] = ws[i].y; p[2] = ws[i].z; p[3] = ws[i].w;
        }
        __syncthreads();

        // ---- stage chunk c+1 loads ----
        if (c + 1 < NCH) {
            const int c0 = (c + 1) * BKQ;
            const float* xp = x + row0 * C_ + c0;
#pragma unroll
            for (int i = 0; i < 2; i++) {
                int v = tid + i * 512;
                int r = v >> 3, cf = v & 7;
                xs[i] = *(const float4*)(xp + (size_t)r * C_ + cf * 4);
            }
            const uint4* wp = (const uint4*)gWhi;
            const uint4* lp = (const uint4*)gWlo;
            const int qoff = c0 / 8;
#pragma unroll
            for (int i = 0; i < 3; i++) {
                int u = tid + i * 512;
                int hi = (u < 768);
                int idx = hi ? u : u - 768;
                int r = idx >> 2, q = idx & 3;
                ws[i] = hi ? wp[r * 48 + qoff + q] : lp[r * 48 + qoff + q];
            }
        }

        // ---- compute chunk c ----
        const uint32_t bufb = sbq + (c & 1) * BUFBY;
#pragma unroll
        for (int ks = 0; ks < 2; ks++) {
            const uint32_t k2 = (uint32_t)(ks * 32);
            uint32_t ah[2][4], al[2][4];
#pragma unroll
            for (int mi = 0; mi < 2; mi++) {
                uint32_t ao = (uint32_t)((wr * 32 + mi * 16) * 80) + k2 + lmA;
                ldm4(ah[mi][0], ah[mi][1], ah[mi][2], ah[mi][3], bufb + AHB + ao);
                ldm4(al[mi][0], al[mi][1], al[mi][2], al[mi][3], bufb + ALB + ao);
            }
#pragma unroll
            for (int npi = 0; npi < 3; npi++) {
                uint32_t bh[4], bl[4];
                uint32_t bo = (uint32_t)((wc * 48 + npi * 16) * 80) + k2 + lmB;
                ldm4(bh[0], bh[1], bh[2], bh[3], bufb + BHB + bo);
                ldm4(bl[0], bl[1], bl[2], bl[3], bufb + BLB + bo);
#pragma unroll
                for (int half = 0; half < 2; half++) {
                    int ni = npi * 2 + half;
                    uint32_t b0 = bh[2 * half], b1 = bh[2 * half + 1];
                    uint32_t c0 = bl[2 * half], c1 = bl[2 * half + 1];
#pragma unroll
                    for (int mi = 0; mi < 2; mi++) {
                        mma16816(acc[mi][ni], ah[mi], b0, b1);
                        mma16816(acc[mi][ni], al[mi], b0, b1);
                        mma16816(acc[mi][ni], ah[mi], c0, c1);
                    }
                }
            }
        }
        // no trailing sync: double buffer + one sync/chunk keeps warps <2 chunks apart
    }

    // ---- epilogue: q/k -> split bf16 planes; v -> split fp16 planes ----
#pragma unroll
    for (int mi = 0; mi < 2; mi++) {
        size_t m0 = row0 + wr * 32 + mi * 16 + g;
#pragma unroll
        for (int ni = 0; ni < 6; ni++) {
            int n = wc * 48 + ni * 8 + tg * 2;
            if (n < 128) {
                __nv_bfloat16 h0, l0, h1, l1, h2, l2, h3, l3;
                split1(acc[mi][ni][0], h0, l0); split1(acc[mi][ni][1], h1, l1);
                split1(acc[mi][ni][2], h2, l2); split1(acc[mi][ni][3], h3, l3);
                __nv_bfloat16* ph = (n < 64) ? g_qh : g_kh;
                __nv_bfloat16* pl = (n < 64) ? g_ql : g_kl;
                int col = n & 63;
                ((uint32_t*)ph)[(m0 * H_ + col) >> 1]       = pack2(h0, h1);
                ((uint32_t*)ph)[((m0 + 8) * H_ + col) >> 1] = pack2(h2, h3);
                ((uint32_t*)pl)[(m0 * H_ + col) >> 1]       = pack2(l0, l1);
                ((uint32_t*)pl)[((m0 + 8) * H_ + col) >> 1] = pack2(l2, l3);
            } else {
                __half h0, l0, h1, l1, h2, l2, h3, l3;
                split1h(acc[mi][ni][0], h0, l0); split1h(acc[mi][ni][1], h1, l1);
                split1h(acc[mi][ni][2], h2, l2); split1h(acc[mi][ni][3], h3, l3);
                int col = n - 128;
                size_t bb = m0 >> 8;
                int t = (int)(m0 & 255);
                size_t base = bb * (size_t)(H_ * T_);
                g_vh[base + col * T_ + t]           = h0;
                g_vh[base + (col + 1) * T_ + t]     = h1;
                g_vh[base + col * T_ + t + 8]       = h2;
                g_vh[base + (col + 1) * T_ + t + 8] = h3;
                g_vl[base + col * T_ + t]           = l0;
                g_vl[base + (col + 1) * T_ + t]     = l1;
                g_vl[base + col * T_ + t + 8]       = l2;
                g_vl[base + (col + 1) * T_ + t + 8] = l3;
            }
        }
    }
}

// ---------------------------------------------------------------------------
// Attention v5: flash + cp.async double buffer; QK bf16 3-term,
// PV fp16: P single-term (plain fp16), V split hi/lo fp16 (2 MMAs, no splits).
// ---------------------------------------------------------------------------
#define KSTB 144
#define PL   (64 * KSTB)
#define BUFA (4 * PL)
#define SMEM2 (2 * BUFA)

__global__ __launch_bounds__(256) void attn(float* __restrict__ out) {
    extern __shared__ char smc[];
    const uint32_t sb = smem_u32(smc);

    const int b    = blockIdx.x;
    const int q0   = blockIdx.y * 128;
    const int tid  = threadIdx.x;
    const int lane = tid & 31;
    const int w    = tid >> 5;
    const int g    = lane >> 2;
    const int tg   = lane & 3;
    const int row0 = q0 + w * 16 + g;

    const uint32_t lmoff =
        (uint32_t)(((lane & 7) + ((lane >> 4) << 3)) * KSTB + ((lane >> 3) & 1) * 16);

    const int lr0 = tid >> 3, lc0 = tid & 7;
    const int lr1 = (tid + 256) >> 3, lc1 = tid & 7;

    auto issue = [&](int kt, int buf) {
        const uint4* KH = (const uint4*)g_kh;
        const uint4* KL = (const uint4*)g_kl;
        const uint4* VH = (const uint4*)g_vh;
        const uint4* VL = (const uint4*)g_vl;
        uint32_t base = sb + buf * BUFA;
#pragma unroll
        for (int i = 0; i < 2; i++) {
            int r  = i ? lr1 : lr0;
            int c8 = i ? lc1 : lc0;
            size_t ksrc = ((size_t)b * T_ + kt * 64 + r) * 8 + c8;
            size_t vsrc = (size_t)b * 2048 + (size_t)r * 32 + kt * 8 + c8;
            uint32_t d = (uint32_t)(r * KSTB + c8 * 16);
            cpa16(base + 0 * PL + d, KH + ksrc);
            cpa16(base + 1 * PL + d, KL + ksrc);
            cpa16(base + 2 * PL + d, VH + vsrc);
            cpa16(base + 3 * PL + d, VL + vsrc);
        }
    };

    // ---- Q fragments (hi/lo) ----
    uint32_t qh[4][4], ql[4][4];
    {
        const size_t rb = (size_t)b * T_ + q0 + w * 16;
        const uint32_t* QH = (const uint32_t*)g_qh;
        const uint32_t* QL = (const uint32_t*)g_ql;
#pragma unroll
        for (int c = 0; c < 4; c++) {
            int d = c * 16 + tg * 2;
            qh[c][0] = QH[((rb + g) * H_ + d) >> 1];
            qh[c][1] = QH[((rb + g + 8) * H_ + d) >> 1];
            qh[c][2] = QH[((rb + g) * H_ + d + 8) >> 1];
            qh[c][3] = QH[((rb + g + 8) * H_ + d + 8) >> 1];
            ql[c][0] = QL[((rb + g) * H_ + d) >> 1];
            ql[c][1] = QL[((rb + g + 8) * H_ + d) >> 1];
            ql[c][2] = QL[((rb + g) * H_ + d + 8) >> 1];
            ql[c][3] = QL[((rb + g + 8) * H_ + d + 8) >> 1];
        }
    }

    float oacc[8][4];
#pragma unroll
    for (int f = 0; f < 8; f++)
#pragma unroll
        for (int r = 0; r < 4; r++) oacc[f][r] = 0.f;
    float m0 = -1e30f, m1 = -1e30f;
    float l0 = 0.f, l1 = 0.f;

    const int ktmax = (q0 + 127) >> 6;

    issue(0, 0);
    CP_COMMIT();

    for (int kt = 0; kt <= ktmax; kt++) {
        if (kt < ktmax) {
            issue(kt + 1, (kt + 1) & 1);
            CP_COMMIT();
            CP_WAIT(1);
        } else {
            CP_WAIT(0);
        }
        __syncthreads();

        if (kt * 64 <= q0 + w * 16 + 15) {
            const uint32_t bb = sb + (kt & 1) * BUFA;
            const uint32_t sKH = bb, sKL = bb + PL, sVH = bb + 2 * PL,
                           sVL = bb + 3 * PL;

            // ---- QK^T (bf16, 3-term) ----
            float sacc[8][4];
#pragma unroll
            for (int f = 0; f < 8; f++)
#pragma unroll
                for (int r = 0; r < 4; r++) sacc[f][r] = 0.f;

#pragma unroll
            for (int c = 0; c < 4; c++) {
                const uint32_t k2 = (uint32_t)(c * 32);
#pragma unroll
                for (int np = 0; np < 4; np++) {
                    uint32_t bh0, bh1, bh2, bh3, bl0, bl1, bl2, bl3;
                    uint32_t a0 = (uint32_t)(np * 16 * KSTB) + k2 + lmoff;
                    ldm4(bh0, bh1, bh2, bh3, sKH + a0);
                    ldm4(bl0, bl1, bl2, bl3, sKL + a0);
                    mma16816(sacc[2 * np],     qh[c], bh0, bh1);
                    mma16816(sacc[2 * np],     ql[c], bh0, bh1);
                    mma16816(sacc[2 * np],     qh[c], bl0, bl1);
                    mma16816(sacc[2 * np + 1], qh[c], bh2, bh3);
                    mma16816(sacc[2 * np + 1], ql[c], bh2, bh3);
                    mma16816(sacc[2 * np + 1], qh[c], bl2, bl3);
                }
            }

            // ---- scale + causal mask ----
            const bool diag = (kt * 64 + 63 > q0 + w * 16);
#pragma unroll
            for (int f = 0; f < 8; f++) {
                int colb = kt * 64 + f * 8 + tg * 2;
                if (diag) {
                    sacc[f][0] = (colb     <= row0) ? sacc[f][0] * 0.125f : -1e30f;
                    sacc[f][1] = (colb + 1 <= row0) ? sacc[f][1] * 0.125f : -1e30f;
                    sacc[f][2] = (colb     <= row0 + 8) ? sacc[f][2] * 0.125f : -1e30f;
                    sacc[f][3] = (colb + 1 <= row0 + 8) ? sacc[f][3] * 0.125f : -1e30f;
                } else {
                    sacc[f][0] *= 0.125f; sacc[f][1] *= 0.125f;
                    sacc[f][2] *= 0.125f; sacc[f][3] *= 0.125f;
                }
            }

            // ---- online softmax update ----
            float t0 = -1e30f, t1 = -1e30f;
#pragma unroll
            for (int f = 0; f < 8; f++) {
                t0 = fmaxf(t0, fmaxf(sacc[f][0], sacc[f][1]));
                t1 = fmaxf(t1, fmaxf(sacc[f][2], sacc[f][3]));
            }
            t0 = fmaxf(t0, __shfl_xor_sync(0xFFFFFFFFu, t0, 1));
            t0 = fmaxf(t0, __shfl_xor_sync(0xFFFFFFFFu, t0, 2));
            t1 = fmaxf(t1, __shfl_xor_sync(0xFFFFFFFFu, t1, 1));
            t1 = fmaxf(t1, __shfl_xor_sync(0xFFFFFFFFu, t1, 2));
            float mn0 = fmaxf(m0, t0), mn1 = fmaxf(m1, t1);
            float a0 = __expf(m0 - mn0), a1 = __expf(m1 - mn1);
            m0 = mn0; m1 = mn1;
            float s0 = 0.f, s1 = 0.f;
#pragma unroll
            for (int f = 0; f < 8; f++) {
                sacc[f][0] = __expf(sacc[f][0] - mn0);
                sacc[f][1] = __expf(sacc[f][1] - mn0);
                sacc[f][2] = __expf(sacc[f][2] - mn1);
                sacc[f][3] = __expf(sacc[f][3] - mn1);
                s0 += sacc[f][0] + sacc[f][1];
                s1 += sacc[f][2] + sacc[f][3];
            }
            l0 = l0 * a0 + s0;
            l1 = l1 * a1 + s1;
#pragma unroll
            for (int f = 0; f < 8; f++) {
                oacc[f][0] *= a0; oacc[f][1] *= a0;
                oacc[f][2] *= a1; oacc[f][3] *= a1;
            }

            // ---- PV (fp16: P single, V hi/lo) ----
#pragma unroll
            for (int c = 0; c < 4; c++) {
                uint32_t p[4];
                p[0] = pack2h(__float2half_rn(sacc[2 * c][0]),
                              __float2half_rn(sacc[2 * c][1]));
                p[1] = pack2h(__float2half_rn(sacc[2 * c][2]),
                              __float2half_rn(sacc[2 * c][3]));
                p[2] = pack2h(__float2half_rn(sacc[2 * c + 1][0]),
                              __float2half_rn(sacc[2 * c + 1][1]));
                p[3] = pack2h(__float2half_rn(sacc[2 * c + 1][2]),
                              __float2half_rn(sacc[2 * c + 1][3]));

                const uint32_t k2 = (uint32_t)(c * 32);
#pragma unroll
                for (int np = 0; np < 4; np++) {
                    uint32_t vh0, vh1, vh2, vh3, vl0, vl1, vl2, vl3;
                    uint32_t a = (uint32_t)(np * 16 * KSTB) + k2 + lmoff;
                    ldm4(vh0, vh1, vh2, vh3, sVH + a);
                    ldm4(vl0, vl1, vl2, vl3, sVL + a);
                    mma16816h(oacc[2 * np],     p, vh0, vh1);
                    mma16816h(oacc[2 * np],     p, vl0, vl1);
                    mma16816h(oacc[2 * np + 1], p, vh2, vh3);
                    mma16816h(oacc[2 * np + 1], p, vl2, vl3);
                }
            }
        }
        __syncthreads();
    }

    // ---- finalize ----
    l0 += __shfl_xor_sync(0xFFFFFFFFu, l0, 1);
    l0 += __shfl_xor_sync(0xFFFFFFFFu, l0, 2);
    l1 += __shfl_xor_sync(0xFFFFFFFFu, l1, 1);
    l1 += __shfl_xor_sync(0xFFFFFFFFu, l1, 2);
    float i0 = 1.f / l0, i1 = 1.f / l1;
    {
        size_t r0 = (size_t)b * T_ + row0;
#pragma unroll
        for (int f = 0; f < 8; f++) {
            int col = f * 8 + tg * 2;
            *(float2*)&out[r0 * H_ + col] =
                make_float2(oacc[f][0] * i0, oacc[f][1] * i0);
            *(float2*)&out[(r0 + 8) * H_ + col] =
                make_float2(oacc[f][2] * i1, oacc[f][3] * i1);
        }
    }
}

// ---------------------------------------------------------------------------
extern "C" void kernel_launch(void* const* d_in, const int* in_sizes, int n_in,
                              void* d_out, int out_size) {
    const float* x  = (const float*)d_in[0];
    const float* Wq = (const float*)d_in[1];
    const float* Wk = (const float*)d_in[2];
    const float* Wv = (const float*)d_in[3];
    float* out = (float*)d_out;
    (void)in_sizes; (void)n_in; (void)out_size;

    cudaFuncSetAttribute(qkv_mma, cudaFuncAttributeMaxDynamicSharedMemorySize, SMEMQ);
    cudaFuncSetAttribute(attn, cudaFuncAttributeMaxDynamicSharedMemorySize, SMEM2);

    wprep<<<(NTOT * C_ + 255) / 256, 256>>>(Wq, Wk, Wv);
    qkv_mma<<<(B_ * T_) / 128, 512, SMEMQ>>>(x);
    attn<<<dim3(B_, T_ / 128), 256, SMEM2>>>(out);
}

// round 11
// speedup vs baseline: 3.5431x; 1.4543x over previous
#include <cuda_runtime.h>
#include <cuda_bf16.h>
#include <cuda_fp16.h>
#include <cstdint>

#define B_ 512
#define T_ 256
#define C_ 384
#define H_ 64
#define NTOT 192

// single-fp16 q (prescaled by 0.125) and k planes, row-major [tok][dim]
__device__ __align__(16) __half g_qs[B_ * T_ * H_];
__device__ __align__(16) __half g_ks[B_ * T_ * H_];
// split-fp16 v planes, transposed per batch [b][dim][tok]
__device__ __align__(16) __half g_vh[B_ * T_ * H_];
__device__ __align__(16) __half g_vl[B_ * T_ * H_];
// single-fp16 weights, K-major [n(q|k|v)][384]
__device__ __align__(16) __half gW[NTOT * C_];

__device__ __forceinline__ void split1h(float v, __half& h, __half& l) {
    h = __float2half_rn(v);
    l = __float2half_rn(v - __half2float(h));
}
__device__ __forceinline__ uint32_t pack2h(__half a, __half b) {
    __half2 t = __halves2half2(a, b);
    uint32_t u; memcpy(&u, &t, 4); return u;
}
__device__ __forceinline__ void mma16816h(float* d, const uint32_t* a,
                                          uint32_t b0, uint32_t b1) {
    asm volatile(
        "mma.sync.aligned.m16n8k16.row.col.f32.f16.f16.f32 "
        "{%0,%1,%2,%3},{%4,%5,%6,%7},{%8,%9},{%0,%1,%2,%3};"
        : "+f"(d[0]), "+f"(d[1]), "+f"(d[2]), "+f"(d[3])
        : "r"(a[0]), "r"(a[1]), "r"(a[2]), "r"(a[3]), "r"(b0), "r"(b1));
}
__device__ __forceinline__ void ldm4(uint32_t& r0, uint32_t& r1, uint32_t& r2,
                                     uint32_t& r3, uint32_t addr) {
    asm volatile("ldmatrix.sync.aligned.m8n8.x4.shared.b16 {%0,%1,%2,%3},[%4];"
                 : "=r"(r0), "=r"(r1), "=r"(r2), "=r"(r3) : "r"(addr));
}
__device__ __forceinline__ uint32_t smem_u32(const void* p) {
    uint32_t a;
    asm("{ .reg .u64 t; cvta.to.shared.u64 t, %1; cvt.u32.u64 %0, t; }"
        : "=r"(a) : "l"(p));
    return a;
}
__device__ __forceinline__ void cpa16(uint32_t dst, const void* src) {
    asm volatile("cp.async.cg.shared.global [%0], [%1], 16;"
                 :: "r"(dst), "l"(src) : "memory");
}
#define CP_COMMIT() asm volatile("cp.async.commit_group;" ::: "memory")
#define CP_WAIT(n)  asm volatile("cp.async.wait_group %0;" :: "n"(n) : "memory")

// ------------------------------------------------------- weight prep (tiny)
__global__ void wprep(const float* __restrict__ Wq, const float* __restrict__ Wk,
                      const float* __restrict__ Wv) {
    int i = blockIdx.x * 256 + threadIdx.x;
    if (i >= NTOT * C_) return;
    int n = i / C_, ck = i % C_;
    const float* W = (n < 64) ? Wq : ((n < 128) ? Wk : Wv);
    gW[i] = __float2half_rn(W[ck * H_ + (n & 63)]);
}

// ---------------------------------------------------------------------------
// QKV projection: x split fp16 (exact) x W single fp16 -> 2-term mma.
// CTA 128 M x 192 N, BK=32, 512 thr, double-buffered smem, ldmatrix.
// ---------------------------------------------------------------------------
#define BKQ 32
#define ASTR 40
#define SM_AH 0
#define SM_AL (128 * ASTR)
#define SM_B  (2 * 128 * ASTR)
#define AHB 0
#define ALB (SM_AL * 2)
#define BB  (SM_B * 2)
#define BUFEL (2 * 128 * ASTR + 192 * ASTR)   // 17920 elements
#define BUFBY (BUFEL * 2)                      // 35840 bytes
#define SMEMQ (2 * BUFBY)                      // 71680 bytes

__global__ __launch_bounds__(512, 1) void qkv_mma(const float* __restrict__ x) {
    extern __shared__ __half sm[];
    const uint32_t sbq = smem_u32(sm);
    const int tid  = threadIdx.x;
    const int w    = tid >> 5;
    const int lane = tid & 31;
    const int g    = lane >> 2;
    const int tg   = lane & 3;
    const int wr   = w >> 2;
    const int wc   = w & 3;
    const size_t row0 = (size_t)blockIdx.x * 128;

    const uint32_t lmA = (uint32_t)((lane & 15) * 80 + (lane >> 4) * 16);
    const uint32_t lmB = (uint32_t)(((lane & 7) + ((lane >> 4) << 3)) * 80 +
                                    ((lane >> 3) & 1) * 16);

    float acc[2][6][4];
#pragma unroll
    for (int mi = 0; mi < 2; mi++)
#pragma unroll
        for (int ni = 0; ni < 6; ni++)
#pragma unroll
            for (int r = 0; r < 4; r++) acc[mi][ni][r] = 0.f;

    float4 xs[2];
    uint4  ws[2];
    {
        const float* xp = x + row0 * C_;
#pragma unroll
        for (int i = 0; i < 2; i++) {
            int v = tid + i * 512;
            int r = v >> 3, cf = v & 7;
            xs[i] = *(const float4*)(xp + (size_t)r * C_ + cf * 4);
        }
        const uint4* wp = (const uint4*)gW;   // rows of 384 fp16 = 48 uint4
#pragma unroll
        for (int i = 0; i < 2; i++) {
            int u = tid + i * 512;
            if (u < 768) {
                int r = u >> 2, q = u & 3;
                ws[i] = wp[r * 48 + q];
            }
        }
    }

    const int NCH = C_ / BKQ;   // 12
    for (int c = 0; c < NCH; c++) {
        __half* smb = sm + (c & 1) * BUFEL;
        // ---- store staged chunk c ----
#pragma unroll
        for (int i = 0; i < 2; i++) {
            int v = tid + i * 512;
            int r = v >> 3, cf = v & 7;
            __half h0, l0, h1, l1, h2, l2, h3, l3;
            split1h(xs[i].x, h0, l0); split1h(xs[i].y, h1, l1);
            split1h(xs[i].z, h2, l2); split1h(xs[i].w, h3, l3);
            uint32_t* ph = (uint32_t*)&smb[SM_AH + r * ASTR + cf * 4];
            uint32_t* pl = (uint32_t*)&smb[SM_AL + r * ASTR + cf * 4];
            ph[0] = pack2h(h0, h1); ph[1] = pack2h(h2, h3);
            pl[0] = pack2h(l0, l1); pl[1] = pack2h(l2, l3);
        }
#pragma unroll
        for (int i = 0; i < 2; i++) {
            int u = tid + i * 512;
            if (u < 768) {
                int r = u >> 2, q = u & 3;
                uint32_t* p = (uint32_t*)&smb[SM_B + r * ASTR + q * 8];
                p[0] = ws[i].x; p[1] = ws[i].y; p[2] = ws[i].z; p[3] = ws[i].w;
            }
        }
        __syncthreads();

        // ---- stage chunk c+1 ----
        if (c + 1 < NCH) {
            const int c0 = (c + 1) * BKQ;
            const float* xp = x + row0 * C_ + c0;
#pragma unroll
            for (int i = 0; i < 2; i++) {
                int v = tid + i * 512;
                int r = v >> 3, cf = v & 7;
                xs[i] = *(const float4*)(xp + (size_t)r * C_ + cf * 4);
            }
            const uint4* wp = (const uint4*)gW;
            const int qoff = c0 / 8;
#pragma unroll
            for (int i = 0; i < 2; i++) {
                int u = tid + i * 512;
                if (u < 768) {
                    int r = u >> 2, q = u & 3;
                    ws[i] = wp[r * 48 + qoff + q];
                }
            }
        }

        // ---- compute chunk c: 2-term fp16 ----
        const uint32_t bufb = sbq + (c & 1) * BUFBY;
#pragma unroll
        for (int ks = 0; ks < 2; ks++) {
            const uint32_t k2 = (uint32_t)(ks * 32);
            uint32_t ah[2][4], al[2][4];
#pragma unroll
            for (int mi = 0; mi < 2; mi++) {
                uint32_t ao = (uint32_t)((wr * 32 + mi * 16) * 80) + k2 + lmA;
                ldm4(ah[mi][0], ah[mi][1], ah[mi][2], ah[mi][3], bufb + AHB + ao);
                ldm4(al[mi][0], al[mi][1], al[mi][2], al[mi][3], bufb + ALB + ao);
            }
#pragma unroll
            for (int npi = 0; npi < 3; npi++) {
                uint32_t bs[4];
                uint32_t bo = (uint32_t)((wc * 48 + npi * 16) * 80) + k2 + lmB;
                ldm4(bs[0], bs[1], bs[2], bs[3], bufb + BB + bo);
#pragma unroll
                for (int half = 0; half < 2; half++) {
                    int ni = npi * 2 + half;
                    uint32_t b0 = bs[2 * half], b1 = bs[2 * half + 1];
#pragma unroll
                    for (int mi = 0; mi < 2; mi++) {
                        mma16816h(acc[mi][ni], ah[mi], b0, b1);
                        mma16816h(acc[mi][ni], al[mi], b0, b1);
                    }
                }
            }
        }
    }

    // ---- epilogue: q (x0.125) / k single fp16; v split fp16 transposed ----
#pragma unroll
    for (int mi = 0; mi < 2; mi++) {
        size_t m0 = row0 + wr * 32 + mi * 16 + g;
#pragma unroll
        for (int ni = 0; ni < 6; ni++) {
            int n = wc * 48 + ni * 8 + tg * 2;
            if (n < 128) {
                float s = (n < 64) ? 0.125f : 1.0f;
                __half* pd = (n < 64) ? g_qs : g_ks;
                int col = n & 63;
                ((uint32_t*)pd)[(m0 * H_ + col) >> 1] =
                    pack2h(__float2half_rn(acc[mi][ni][0] * s),
                           __float2half_rn(acc[mi][ni][1] * s));
                ((uint32_t*)pd)[((m0 + 8) * H_ + col) >> 1] =
                    pack2h(__float2half_rn(acc[mi][ni][2] * s),
                           __float2half_rn(acc[mi][ni][3] * s));
            } else {
                __half h0, l0, h1, l1, h2, l2, h3, l3;
                split1h(acc[mi][ni][0], h0, l0); split1h(acc[mi][ni][1], h1, l1);
                split1h(acc[mi][ni][2], h2, l2); split1h(acc[mi][ni][3], h3, l3);
                int col = n - 128;
                size_t bb = m0 >> 8;
                int t = (int)(m0 & 255);
                size_t base = bb * (size_t)(H_ * T_);
                g_vh[base + col * T_ + t]           = h0;
                g_vh[base + (col + 1) * T_ + t]     = h1;
                g_vh[base + col * T_ + t + 8]       = h2;
                g_vh[base + (col + 1) * T_ + t + 8] = h3;
                g_vl[base + col * T_ + t]           = l0;
                g_vl[base + (col + 1) * T_ + t]     = l1;
                g_vl[base + col * T_ + t + 8]       = l2;
                g_vl[base + (col + 1) * T_ + t + 8] = l3;
            }
        }
    }
}

// ---------------------------------------------------------------------------
// Attention v6: flash + cp.async double buffer.
// QK: single fp16 (q prescaled), 1 MMA. PV: P fp16 single, V fp16 hi/lo.
// ---------------------------------------------------------------------------
#define KSTB 144
#define PL   (64 * KSTB)               // 9216 B per plane
#define BUFA (3 * PL)                  // 27648 B (K, VH, VL)
#define SMEM2 (2 * BUFA)               // 55296 B

__global__ __launch_bounds__(256) void attn(float* __restrict__ out) {
    extern __shared__ char smc[];
    const uint32_t sb = smem_u32(smc);

    const int b    = blockIdx.x;
    const int q0   = blockIdx.y * 128;
    const int tid  = threadIdx.x;
    const int lane = tid & 31;
    const int w    = tid >> 5;
    const int g    = lane >> 2;
    const int tg   = lane & 3;
    const int row0 = q0 + w * 16 + g;

    const uint32_t lmoff =
        (uint32_t)(((lane & 7) + ((lane >> 4) << 3)) * KSTB + ((lane >> 3) & 1) * 16);

    const int lr0 = tid >> 3, lc0 = tid & 7;
    const int lr1 = (tid + 256) >> 3, lc1 = tid & 7;

    auto issue = [&](int kt, int buf) {
        const uint4* KS = (const uint4*)g_ks;
        const uint4* VH = (const uint4*)g_vh;
        const uint4* VL = (const uint4*)g_vl;
        uint32_t base = sb + buf * BUFA;
#pragma unroll
        for (int i = 0; i < 2; i++) {
            int r  = i ? lr1 : lr0;
            int c8 = i ? lc1 : lc0;
            size_t ksrc = ((size_t)b * T_ + kt * 64 + r) * 8 + c8;
            size_t vsrc = (size_t)b * 2048 + (size_t)r * 32 + kt * 8 + c8;
            uint32_t d = (uint32_t)(r * KSTB + c8 * 16);
            cpa16(base + 0 * PL + d, KS + ksrc);
            cpa16(base + 1 * PL + d, VH + vsrc);
            cpa16(base + 2 * PL + d, VL + vsrc);
        }
    };

    // ---- Q fragments (single fp16, prescaled by 0.125) ----
    uint32_t qf[4][4];
    {
        const size_t rb = (size_t)b * T_ + q0 + w * 16;
        const uint32_t* QS = (const uint32_t*)g_qs;
#pragma unroll
        for (int c = 0; c < 4; c++) {
            int d = c * 16 + tg * 2;
            qf[c][0] = QS[((rb + g) * H_ + d) >> 1];
            qf[c][1] = QS[((rb + g + 8) * H_ + d) >> 1];
            qf[c][2] = QS[((rb + g) * H_ + d + 8) >> 1];
            qf[c][3] = QS[((rb + g + 8) * H_ + d + 8) >> 1];
        }
    }

    float oacc[8][4];
#pragma unroll
    for (int f = 0; f < 8; f++)
#pragma unroll
        for (int r = 0; r < 4; r++) oacc[f][r] = 0.f;
    float m0 = -1e30f, m1 = -1e30f;
    float l0 = 0.f, l1 = 0.f;

    const int ktmax = (q0 + 127) >> 6;

    issue(0, 0);
    CP_COMMIT();

    for (int kt = 0; kt <= ktmax; kt++) {
        if (kt < ktmax) {
            issue(kt + 1, (kt + 1) & 1);
            CP_COMMIT();
            CP_WAIT(1);
        } else {
            CP_WAIT(0);
        }
        __syncthreads();

        if (kt * 64 <= q0 + w * 16 + 15) {
            const uint32_t bb = sb + (kt & 1) * BUFA;
            const uint32_t sK = bb, sVH = bb + PL, sVL = bb + 2 * PL;

            // ---- QK^T (single fp16) ----
            float sacc[8][4];
#pragma unroll
            for (int f = 0; f < 8; f++)
#pragma unroll
                for (int r = 0; r < 4; r++) sacc[f][r] = 0.f;

#pragma unroll
            for (int c = 0; c < 4; c++) {
                const uint32_t k2 = (uint32_t)(c * 32);
#pragma unroll
                for (int np = 0; np < 4; np++) {
                    uint32_t b0, b1, b2, b3;
                    uint32_t a0 = (uint32_t)(np * 16 * KSTB) + k2 + lmoff;
                    ldm4(b0, b1, b2, b3, sK + a0);
                    mma16816h(sacc[2 * np],     qf[c], b0, b1);
                    mma16816h(sacc[2 * np + 1], qf[c], b2, b3);
                }
            }

            // ---- causal mask (scale prefolded into q) ----
            if (kt * 64 + 63 > q0 + w * 16) {
#pragma unroll
                for (int f = 0; f < 8; f++) {
                    int colb = kt * 64 + f * 8 + tg * 2;
                    if (colb     > row0)     sacc[f][0] = -1e30f;
                    if (colb + 1 > row0)     sacc[f][1] = -1e30f;
                    if (colb     > row0 + 8) sacc[f][2] = -1e30f;
                    if (colb + 1 > row0 + 8) sacc[f][3] = -1e30f;
                }
            }

            // ---- online softmax update ----
            float t0 = -1e30f, t1 = -1e30f;
#pragma unroll
            for (int f = 0; f < 8; f++) {
                t0 = fmaxf(t0, fmaxf(sacc[f][0], sacc[f][1]));
                t1 = fmaxf(t1, fmaxf(sacc[f][2], sacc[f][3]));
            }
            t0 = fmaxf(t0, __shfl_xor_sync(0xFFFFFFFFu, t0, 1));
            t0 = fmaxf(t0, __shfl_xor_sync(0xFFFFFFFFu, t0, 2));
            t1 = fmaxf(t1, __shfl_xor_sync(0xFFFFFFFFu, t1, 1));
            t1 = fmaxf(t1, __shfl_xor_sync(0xFFFFFFFFu, t1, 2));
            float mn0 = fmaxf(m0, t0), mn1 = fmaxf(m1, t1);
            float a0 = __expf(m0 - mn0), a1 = __expf(m1 - mn1);
            m0 = mn0; m1 = mn1;
            float s0 = 0.f, s1 = 0.f;
#pragma unroll
            for (int f = 0; f < 8; f++) {
                sacc[f][0] = __expf(sacc[f][0] - mn0);
                sacc[f][1] = __expf(sacc[f][1] - mn0);
                sacc[f][2] = __expf(sacc[f][2] - mn1);
                sacc[f][3] = __expf(sacc[f][3] - mn1);
                s0 += sacc[f][0] + sacc[f][1];
                s1 += sacc[f][2] + sacc[f][3];
            }
            l0 = l0 * a0 + s0;
            l1 = l1 * a1 + s1;
#pragma unroll
            for (int f = 0; f < 8; f++) {
                oacc[f][0] *= a0; oacc[f][1] *= a0;
                oacc[f][2] *= a1; oacc[f][3] *= a1;
            }

            // ---- PV (P single fp16, V hi/lo) ----
#pragma unroll
            for (int c = 0; c < 4; c++) {
                uint32_t p[4];
                p[0] = pack2h(__float2half_rn(sacc[2 * c][0]),
                              __float2half_rn(sacc[2 * c][1]));
                p[1] = pack2h(__float2half_rn(sacc[2 * c][2]),
                              __float2half_rn(sacc[2 * c][3]));
                p[2] = pack2h(__float2half_rn(sacc[2 * c + 1][0]),
                              __float2half_rn(sacc[2 * c + 1][1]));
                p[3] = pack2h(__float2half_rn(sacc[2 * c + 1][2]),
                              __float2half_rn(sacc[2 * c + 1][3]));

                const uint32_t k2 = (uint32_t)(c * 32);
#pragma unroll
                for (int np = 0; np < 4; np++) {
                    uint32_t vh0, vh1, vh2, vh3, vl0, vl1, vl2, vl3;
                    uint32_t a = (uint32_t)(np * 16 * KSTB) + k2 + lmoff;
                    ldm4(vh0, vh1, vh2, vh3, sVH + a);
                    ldm4(vl0, vl1, vl2, vl3, sVL + a);
                    mma16816h(oacc[2 * np],     p, vh0, vh1);
                    mma16816h(oacc[2 * np],     p, vl0, vl1);
                    mma16816h(oacc[2 * np + 1], p, vh2, vh3);
                    mma16816h(oacc[2 * np + 1], p, vl2, vl3);
                }
            }
        }
        __syncthreads();
    }

    // ---- finalize ----
    l0 += __shfl_xor_sync(0xFFFFFFFFu, l0, 1);
    l0 += __shfl_xor_sync(0xFFFFFFFFu, l0, 2);
    l1 += __shfl_xor_sync(0xFFFFFFFFu, l1, 1);
    l1 += __shfl_xor_sync(0xFFFFFFFFu, l1, 2);
    float i0 = 1.f / l0, i1 = 1.f / l1;
    {
        size_t r0 = (size_t)b * T_ + row0;
#pragma unroll
        for (int f = 0; f < 8; f++) {
            int col = f * 8 + tg * 2;
            *(float2*)&out[r0 * H_ + col] =
                make_float2(oacc[f][0] * i0, oacc[f][1] * i0);
            *(float2*)&out[(r0 + 8) * H_ + col] =
                make_float2(oacc[f][2] * i1, oacc[f][3] * i1);
        }
    }
}

// ---------------------------------------------------------------------------
extern "C" void kernel_launch(void* const* d_in, const int* in_sizes, int n_in,
                              void* d_out, int out_size) {
    const float* x  = (const float*)d_in[0];
    const float* Wq = (const float*)d_in[1];
    const float* Wk = (const float*)d_in[2];
    const float* Wv = (const float*)d_in[3];
    float* out = (float*)d_out;
    (void)in_sizes; (void)n_in; (void)out_size;

    cudaFuncSetAttribute(qkv_mma, cudaFuncAttributeMaxDynamicSharedMemorySize, SMEMQ);
    cudaFuncSetAttribute(attn, cudaFuncAttributeMaxDynamicSharedMemorySize, SMEM2);

    wprep<<<(NTOT * C_ + 255) / 256, 256>>>(Wq, Wk, Wv);
    qkv_mma<<<(B_ * T_) / 128, 512, SMEMQ>>>(x);
    attn<<<dim3(B_, T_ / 128), 256, SMEM2>>>(out);
}